// round 12
// baseline (speedup 1.0000x reference)
#include <cuda_runtime.h>
#include <cuda_bf16.h>
#include <math.h>

#define Bq 4
#define Lq 4096
#define Hq 256
#define NHq 8
#define Tq 64
#define Dq 32
#define WINq 16
#define NEG_SLOPE 5.0f
#define MASK_FILL -1e12f

// ---------------- scratch (device globals; no allocation allowed) ----------------
__device__ float g_types_h[Bq * Tq * Hq];
__device__ float g_ch[Bq * Lq * Hq];
__device__ float g_U[Bq * Lq * Hq];
__device__ float g_uq[Bq * NHq * Lq];
__device__ float g_ds[Bq * NHq * Lq];
__device__ float g_dt[Bq * NHq * Tq];
__device__ unsigned g_WtHi[3 * 256 * 128];
__device__ unsigned g_WtLo[3 * 256 * 128];
// packed bf16x2 hi/lo operand copies (x = hi, y = lo)
__device__ uint2 g_chP2[Bq * NHq * Lq * 16];      // row-major ch   [b][n][l][kp]
__device__ uint2 g_chT2[Bq * NHq * 32 * 2048];    // transposed ch  [b][n][d][lp]
__device__ uint2 g_tyP2[Bq * NHq * 64 * 16];      // row-major types
__device__ uint2 g_tyT2[Bq * NHq * 32 * 32];      // transposed types
__device__ uint2 g_xP2[NHq * 32 * 16];            // crossT [n][h][kp]

__device__ __forceinline__ float leaky(float x) { return x >= 0.f ? x : NEG_SLOPE * x; }

__device__ __forceinline__ unsigned pack_bf16x2(float lo_elem, float hi_elem) {
    unsigned r;
    asm("cvt.rn.bf16x2.f32 %0, %1, %2;" : "=r"(r) : "f"(hi_elem), "f"(lo_elem));
    return r;
}
__device__ __forceinline__ float bf_lo(unsigned p) { return __uint_as_float(p << 16); }
__device__ __forceinline__ float bf_hi(unsigned p) { return __uint_as_float(p & 0xFFFF0000u); }

__device__ __forceinline__ void mma16bf(float c[4], const unsigned a[4], const unsigned b[2]) {
    asm volatile(
        "mma.sync.aligned.m16n8k16.row.col.f32.bf16.bf16.f32 "
        "{%0,%1,%2,%3}, {%4,%5,%6,%7}, {%8,%9}, {%0,%1,%2,%3};"
        : "+f"(c[0]), "+f"(c[1]), "+f"(c[2]), "+f"(c[3])
        : "r"(a[0]), "r"(a[1]), "r"(a[2]), "r"(a[3]), "r"(b[0]), "r"(b[1]));
}
__device__ __forceinline__ void mma3(float c[4],
                                     const unsigned ahi[4], const unsigned alo[4],
                                     const unsigned bhi[2], const unsigned blo[2]) {
    mma16bf(c, ahi, bhi);
    mma16bf(c, ahi, blo);
    mma16bf(c, alo, bhi);
}

__device__ __forceinline__ void gatherA16(const unsigned* U, int stride,
                                          int R0, int KP0, int lane, unsigned a[4]) {
    int p = (R0 + (lane >> 2)) * stride + KP0 + (lane & 3);
    a[0] = U[p];
    a[1] = U[p + 8 * stride];
    a[2] = U[p + 4];
    a[3] = U[p + 8 * stride + 4];
}
__device__ __forceinline__ void gatherB16(const unsigned* U, int stride,
                                          int N0, int KP0, int lane, unsigned bb[2]) {
    int p = (N0 + (lane >> 2)) * stride + KP0 + (lane & 3);
    bb[0] = U[p];
    bb[1] = U[p + 4];
}

__device__ __forceinline__ void store_split(unsigned* baseHi, unsigned* baseLo,
                                            int halfIdx, float v) {
    __nv_bfloat16 h = __float2bfloat16(v);
    float r = v - __bfloat162float(h);
    ((__nv_bfloat16*)baseHi)[halfIdx] = h;
    ((__nv_bfloat16*)baseLo)[halfIdx] = __float2bfloat16(r);
}

__device__ __forceinline__ int mask_mode(const void* m) {
    unsigned u = *(const unsigned*)m;
    if (u == 0x01010101u) return 0;
    if (u == 0x3F800000u) return 2;
    return 1;
}
__device__ __forceinline__ bool mask_at(const void* m, int mode, long idx) {
    if (mode == 0) return ((const unsigned char*)m)[idx] != 0;
    if (mode == 1) return ((const int*)m)[idx] != 0;
    return ((const float*)m)[idx] != 0.f;
}

// swizzled smem read for pack_ops tiles (stride 36, xor-rotated float4 groups)
__device__ __forceinline__ float sread(const float* s, int row, int col) {
    return s[row * 36 + ((((col >> 2) + row) & 7) << 2) + (col & 3)];
}

// ---------------- prep: transpose + bf16-split the three 256x256 weights -------
__global__ __launch_bounds__(256) void prep_weights(
    const float* __restrict__ W0, const float* __restrict__ W1,
    const float* __restrict__ W2)
{
    __shared__ float s[32][33];
    const int w = blockIdx.z;
    const float* W = (w == 0) ? W0 : (w == 1) ? W1 : W2;
    const int k0 = blockIdx.x * 32, n0 = blockIdx.y * 32;
    const int tid = threadIdx.x;
#pragma unroll
    for (int it = 0; it < 4; it++) {
        int idx = it * 256 + tid;
        int kr = idx >> 5, nc = idx & 31;
        s[kr][nc] = W[(size_t)(k0 + kr) * 256 + n0 + nc];
    }
    __syncthreads();
#pragma unroll
    for (int it = 0; it < 2; it++) {
        int idx = it * 256 + tid;
        int nn = idx >> 4, kp = idx & 15;
        float e0 = s[2 * kp][nn], e1 = s[2 * kp + 1][nn];
        unsigned hi = pack_bf16x2(e0, e1);
        unsigned lo = pack_bf16x2(e0 - bf_lo(hi), e1 - bf_hi(hi));
        size_t o = (size_t)(w * 256 + n0 + nn) * 128 + (k0 >> 1) + kp;
        g_WtHi[o] = hi;
        g_WtLo[o] = lo;
    }
}

// ---------------- prep: pack crossT per head ------------------------------------
__global__ __launch_bounds__(256) void prep_cross(const float* __restrict__ cross)
{
    const int tid = threadIdx.x;
#pragma unroll
    for (int it = 0; it < 16; it++) {
        int idx = it * 256 + tid;
        int n = idx >> 9;
        int h = (idx >> 4) & 31;
        int kp = idx & 15;
        float e0 = cross[(size_t)(n * 32 + 2 * kp) * 32 + h];
        float e1 = cross[(size_t)(n * 32 + 2 * kp + 1) * 32 + h];
        unsigned hi = pack_bf16x2(e0, e1);
        unsigned lo = pack_bf16x2(e0 - bf_lo(hi), e1 - bf_hi(hi));
        g_xP2[idx] = make_uint2(hi, lo);
    }
}

// ---------------- pack ch/types into bf16x2 hi/lo operand copies ----------------
// blockIdx.x 0..15: ch chunk of 256 l's; blockIdx.x == 16: types (64 rows)
__global__ __launch_bounds__(256) void pack_ops()
{
    __shared__ float s[256 * 36];
    const int tid = threadIdx.x;
    const int n = blockIdx.y, b = blockIdx.z;
    const int b8n = b * NHq + n;

    if (blockIdx.x < 16) {
        const int l0 = blockIdx.x * 256;
#pragma unroll
        for (int it = 0; it < 8; it++) {
            int idx = it * 256 + tid;
            int row = idx >> 3, f4 = idx & 7;
            float4 v = *(const float4*)(g_ch + (size_t)(b * Lq + l0 + row) * Hq + n * 32 + f4 * 4);
            *(float4*)&s[row * 36 + (((f4 + row) & 7) << 2)] = v;
        }
        __syncthreads();
#pragma unroll
        for (int it = 0; it < 16; it++) {
            int idx = it * 256 + tid;
            int row = idx >> 4, kp = idx & 15;
            float e0 = sread(s, row, 2 * kp), e1 = sread(s, row, 2 * kp + 1);
            unsigned hi = pack_bf16x2(e0, e1);
            unsigned lo = pack_bf16x2(e0 - bf_lo(hi), e1 - bf_hi(hi));
            g_chP2[((size_t)b8n * 4096 + l0 + row) * 16 + kp] = make_uint2(hi, lo);
        }
#pragma unroll
        for (int it = 0; it < 16; it++) {
            int idx = it * 256 + tid;
            int d = idx >> 7, lp = idx & 127;
            float e0 = sread(s, 2 * lp, d), e1 = sread(s, 2 * lp + 1, d);
            unsigned hi = pack_bf16x2(e0, e1);
            unsigned lo = pack_bf16x2(e0 - bf_lo(hi), e1 - bf_hi(hi));
            g_chT2[((size_t)b8n * 32 + d) * 2048 + (l0 >> 1) + lp] = make_uint2(hi, lo);
        }
    } else {
#pragma unroll
        for (int it = 0; it < 2; it++) {
            int idx = it * 256 + tid;
            int row = idx >> 3, f4 = idx & 7;
            float4 v = *(const float4*)(g_types_h + (size_t)(b * Tq + row) * Hq + n * 32 + f4 * 4);
            *(float4*)&s[row * 36 + (((f4 + row) & 7) << 2)] = v;
        }
        __syncthreads();
#pragma unroll
        for (int it = 0; it < 4; it++) {
            int idx = it * 256 + tid;
            int row = idx >> 4, kp = idx & 15;
            float e0 = sread(s, row, 2 * kp), e1 = sread(s, row, 2 * kp + 1);
            unsigned hi = pack_bf16x2(e0, e1);
            unsigned lo = pack_bf16x2(e0 - bf_lo(hi), e1 - bf_hi(hi));
            g_tyP2[((size_t)b8n * 64 + row) * 16 + kp] = make_uint2(hi, lo);
        }
#pragma unroll
        for (int it = 0; it < 4; it++) {
            int idx = it * 256 + tid;
            int d = idx >> 5, lp = idx & 31;
            float e0 = sread(s, 2 * lp, d), e1 = sread(s, 2 * lp + 1, d);
            unsigned hi = pack_bf16x2(e0, e1);
            unsigned lo = pack_bf16x2(e0 - bf_lo(hi), e1 - bf_hi(hi));
            g_tyT2[((size_t)b8n * 32 + d) * 32 + lp] = make_uint2(hi, lo);
        }
    }
}

// ---------------- bf16x3 GEMM + fused row-dot epilogue (R10 version) ------------
// mode: 0 = plain (+tanh), 1 = uq/ds (rows b*L+l), 2 = dt (rows b*T+t)
__global__ __launch_bounds__(256) void gemm_bf16x3(
    const float* __restrict__ A, int wsel,
    const float* __restrict__ bias, float* __restrict__ C,
    int dotanh, int mode,
    const float* __restrict__ upon, const float* __restrict__ down)
{
    __shared__ unsigned sAhi[128 * 20];
    __shared__ unsigned sAlo[128 * 20];
    __shared__ unsigned sBhi[64 * 20];
    __shared__ unsigned sBlo[64 * 20];

    const int tid = threadIdx.x;
    const int wid = tid >> 5, lane = tid & 31;
    const int wm = wid >> 1, wn = wid & 1;
    const int bm = blockIdx.y * 128;
    const int bn = blockIdx.x * 64;
    const unsigned* WHi = g_WtHi + (size_t)wsel * 256 * 128;
    const unsigned* WLo = g_WtLo + (size_t)wsel * 256 * 128;

    float acc[2][4][4];
#pragma unroll
    for (int mt = 0; mt < 2; mt++)
#pragma unroll
        for (int nt = 0; nt < 4; nt++)
#pragma unroll
            for (int r = 0; r < 4; r++) acc[mt][nt][r] = 0.f;

    for (int chunk = 0; chunk < 8; chunk++) {
        const int kc0 = chunk * 32;
#pragma unroll
        for (int i = 0; i < 4; i++) {
            int fidx = i * 256 + tid;
            int row = fidx >> 3, col4 = fidx & 7;
            float4 v = *(const float4*)(A + (size_t)(bm + row) * 256 + kc0 + col4 * 4);
            unsigned h0 = pack_bf16x2(v.x, v.y);
            unsigned h1 = pack_bf16x2(v.z, v.w);
            unsigned l0 = pack_bf16x2(v.x - bf_lo(h0), v.y - bf_hi(h0));
            unsigned l1 = pack_bf16x2(v.z - bf_lo(h1), v.w - bf_hi(h1));
            int o = row * 20 + col4 * 2;
            *(uint2*)&sAhi[o] = make_uint2(h0, h1);
            *(uint2*)&sAlo[o] = make_uint2(l0, l1);
        }
#pragma unroll
        for (int i = 0; i < 2; i++) {
            int fidx = i * 256 + tid;
            int row = fidx >> 3, j = fidx & 7;
            size_t src = (size_t)(bn + row) * 128 + (kc0 >> 1) + j * 2;
            int o = row * 20 + j * 2;
            *(uint2*)&sBhi[o] = *(const uint2*)&WHi[src];
            *(uint2*)&sBlo[o] = *(const uint2*)&WLo[src];
        }
        __syncthreads();
#pragma unroll
        for (int k16 = 0; k16 < 2; k16++) {
            unsigned ahi[2][4], alo[2][4];
#pragma unroll
            for (int mt = 0; mt < 2; mt++) {
                gatherA16(sAhi, 20, wm * 32 + mt * 16, k16 * 8, lane, ahi[mt]);
                gatherA16(sAlo, 20, wm * 32 + mt * 16, k16 * 8, lane, alo[mt]);
            }
#pragma unroll
            for (int nt = 0; nt < 4; nt++) {
                unsigned bhi[2], blo[2];
                gatherB16(sBhi, 20, wn * 32 + nt * 8, k16 * 8, lane, bhi);
                gatherB16(sBlo, 20, wn * 32 + nt * 8, k16 * 8, lane, blo);
#pragma unroll
                for (int mt = 0; mt < 2; mt++) {
                    mma16bf(acc[mt][nt], ahi[mt], bhi);
                    mma16bf(acc[mt][nt], ahi[mt], blo);
                    mma16bf(acc[mt][nt], alo[mt], bhi);
                }
            }
        }
        __syncthreads();
    }

    const int row0 = bm + wm * 32 + (lane >> 2);
    const int col0 = bn + wn * 32 + (lane & 3) * 2;
    float pa[4] = {0.f, 0.f, 0.f, 0.f};
    float pd[4] = {0.f, 0.f, 0.f, 0.f};
#pragma unroll
    for (int mt = 0; mt < 2; mt++)
#pragma unroll
        for (int nt = 0; nt < 4; nt++) {
            int r = row0 + mt * 16;
            int c = col0 + nt * 8;
            float b0 = bias[c], b1 = bias[c + 1];
            float v00 = acc[mt][nt][0] + b0, v01 = acc[mt][nt][1] + b1;
            float v10 = acc[mt][nt][2] + b0, v11 = acc[mt][nt][3] + b1;
            if (mode == 1) {
                float u0 = upon[c], u1 = upon[c + 1];
                float d0 = down[c], d1 = down[c + 1];
                pa[mt * 2 + 0] += v00 * u0 + v01 * u1;
                pa[mt * 2 + 1] += v10 * u0 + v11 * u1;
                pd[mt * 2 + 0] += v00 * d0 + v01 * d1;
                pd[mt * 2 + 1] += v10 * d0 + v11 * d1;
            } else if (mode == 2) {
                float d0 = down[c], d1 = down[c + 1];
                pd[mt * 2 + 0] += v00 * d0 + v01 * d1;
                pd[mt * 2 + 1] += v10 * d0 + v11 * d1;
            }
            float2 o0 = make_float2(v00, v01);
            float2 o1 = make_float2(v10, v11);
            if (dotanh) {
                o0.x = tanhf(o0.x); o0.y = tanhf(o0.y);
                o1.x = tanhf(o1.x); o1.y = tanhf(o1.y);
            }
            *(float2*)(C + (size_t)r * 256 + c)       = o0;
            *(float2*)(C + (size_t)(r + 8) * 256 + c) = o1;
        }

    if (mode) {
#pragma unroll
        for (int j = 0; j < 4; j++) {
            pa[j] += __shfl_xor_sync(0xFFFFFFFFu, pa[j], 1);
            pa[j] += __shfl_xor_sync(0xFFFFFFFFu, pa[j], 2);
            pd[j] += __shfl_xor_sync(0xFFFFFFFFu, pd[j], 1);
            pd[j] += __shfl_xor_sync(0xFFFFFFFFu, pd[j], 2);
        }
        if ((lane & 3) == 0) {
            const int hn = (bn >> 5) + wn;
#pragma unroll
            for (int j = 0; j < 4; j++) {
                int row = row0 + (j >> 1) * 16 + (j & 1) * 8;
                if (mode == 1) {
                    int b = row >> 12, l = row & 4095;
                    g_uq[((size_t)(b * NHq + hn)) * Lq + l] = pa[j];
                    g_ds[((size_t)(b * NHq + hn)) * Lq + l] = pd[j];
                } else {
                    int b = row >> 6, t = row & 63;
                    g_dt[(b * NHq + hn) * Tq + t] = pd[j];
                }
            }
        }
    }
}

// ---------------- attention core v6: pre-packed operands, fat tiles -------------
#define OFF_XT    0
#define OFF_CHa   1280
#define OFF_TY    4480
#define OFF_CQ    7040
#define OFF_WW    0
#define OFF_WT    5632
#define OFF_TT    10240
#define OFF_CT    12544
#define OFF_LT    15360
#define OFF_G     19712
#define OFF_UQ    21056
#define OFF_DS    21136
#define OFF_MK    21216
#define OFF_DT    21296
#define SMEM_UINTS 21360
#define ATTN_SMEM_BYTES (SMEM_UINTS * 4)

__global__ __launch_bounds__(512, 2) void attn_mma6_kernel(
    const void* __restrict__ maskp, const float* __restrict__ context)
{
    extern __shared__ unsigned SU[];
    float* SF = (float*)SU;
    const int tid = threadIdx.x, wid = tid >> 5, lane = tid & 31;
    const int n = blockIdx.y, b = blockIdx.z;
    const int l0 = blockIdx.x * 64;
    const int mmode = mask_mode(maskp);
    const int b8n = b * NHq + n;
    const int bnL = b8n * Lq;
    const long maskbase = (long)b * Lq;

    // ---------------- stage (pure uint2 copies) ----------------
    for (int i = tid; i < 1280; i += 512) {
        int row = i >> 4, kp = i & 15;
        int l = l0 + row; if (l > Lq - 1) l = Lq - 1;
        uint2 w = g_chP2[((size_t)b8n * 4096 + l) * 16 + kp];
        SU[OFF_CHa + row * 20 + kp] = w.x;
        SU[OFF_CHa + 1600 + row * 20 + kp] = w.y;
    }
    for (int i = tid; i < 1280; i += 512) {
        int d = i / 40, lp = i - d * 40;
        int lpa = (l0 >> 1) + lp; if (lpa > 2047) lpa = 2047;
        uint2 w = g_chT2[((size_t)b8n * 32 + d) * 2048 + lpa];
        SU[OFF_CT + d * 44 + lp] = w.x;
        SU[OFF_CT + 1408 + d * 44 + lp] = w.y;
    }
    for (int i = tid; i < 1024; i += 512) {
        uint2 w = g_tyP2[(size_t)b8n * 1024 + i];
        int t = i >> 4, kp = i & 15;
        SU[OFF_TY + t * 20 + kp] = w.x;
        SU[OFF_TY + 1280 + t * 20 + kp] = w.y;
    }
    for (int i = tid; i < 1024; i += 512) {
        uint2 w = g_tyT2[(size_t)b8n * 1024 + i];
        int d = i >> 5, lp = i & 31;
        SU[OFF_TT + d * 36 + lp] = w.x;
        SU[OFF_TT + 1152 + d * 36 + lp] = w.y;
    }
    {
        int i = tid;
        if (i < 512) {
            uint2 w = g_xP2[n * 512 + i];
            int h = i >> 4, kp = i & 15;
            SU[OFF_XT + h * 20 + kp] = w.x;
            SU[OFF_XT + 640 + h * 20 + kp] = w.y;
        }
    }
    for (int i = tid; i < 80; i += 512) {
        int ru = l0 + i; if (ru > Lq - 1) ru = Lq - 1;
        SF[OFF_UQ + i] = g_uq[bnL + ru];
        SF[OFF_MK + i] = mask_at(maskp, mmode, maskbase + ru) ? 1.f : 0.f;
        int rd = l0 + i - 16; if (rd < 0) rd = 0;
        SF[OFF_DS + i] = g_ds[bnL + rd];
    }
    for (int i = tid; i < 64; i += 512) SF[OFF_DT + i] = g_dt[b8n * Tq + i];
    __syncthreads();

    // ---------------- phase A: CQ = CH @ crossT (8 fat warps) ----------------
    if (wid < 8) {
        const int mt = wid >> 1, nhp = wid & 1;
        float acc[2][4] = {{0,0,0,0},{0,0,0,0}};
#pragma unroll
        for (int k16 = 0; k16 < 2; k16++) {
            unsigned ahi[4], alo[4];
            gatherA16(SU + OFF_CHa, 20, mt * 16, k16 * 8, lane, ahi);
            gatherA16(SU + OFF_CHa + 1600, 20, mt * 16, k16 * 8, lane, alo);
#pragma unroll
            for (int j = 0; j < 2; j++) {
                unsigned bhi[2], blo[2];
                gatherB16(SU + OFF_XT, 20, (nhp * 2 + j) * 8, k16 * 8, lane, bhi);
                gatherB16(SU + OFF_XT + 640, 20, (nhp * 2 + j) * 8, k16 * 8, lane, blo);
                mma3(acc[j], ahi, alo, bhi, blo);
            }
        }
        const int rlo = mt * 16 + (lane >> 2);
#pragma unroll
        for (int j = 0; j < 2; j++) {
            const int cp = (nhp * 2 + j) * 4 + (lane & 3);
            unsigned h0 = pack_bf16x2(acc[j][0], acc[j][1]);
            unsigned l0p = pack_bf16x2(acc[j][0] - bf_lo(h0), acc[j][1] - bf_hi(h0));
            unsigned h1 = pack_bf16x2(acc[j][2], acc[j][3]);
            unsigned l1p = pack_bf16x2(acc[j][2] - bf_lo(h1), acc[j][3] - bf_hi(h1));
            SU[OFF_CQ + rlo * 20 + cp]              = h0;
            SU[OFF_CQ + 1280 + rlo * 20 + cp]       = l0p;
            SU[OFF_CQ + (rlo + 8) * 20 + cp]        = h1;
            SU[OFF_CQ + 1280 + (rlo + 8) * 20 + cp] = l1p;
        }
    }
    __syncthreads();

    // ---------------- phase B: logits (warps 0-7) / band G (warps 8-11) -------
    if (wid < 8) {
        const int mt = wid >> 1, half = wid & 1;
        float acc2[4][4];
#pragma unroll
        for (int i = 0; i < 4; i++)
#pragma unroll
            for (int r = 0; r < 4; r++) acc2[i][r] = 0.f;
#pragma unroll
        for (int k16 = 0; k16 < 2; k16++) {
            unsigned ahi[4], alo[4];
            gatherA16(SU + OFF_CQ, 20, mt * 16, k16 * 8, lane, ahi);
            gatherA16(SU + OFF_CQ + 1280, 20, mt * 16, k16 * 8, lane, alo);
#pragma unroll
            for (int j = 0; j < 4; j++) {
                int ntg = half * 4 + j;
                unsigned bhi[2], blo[2];
                gatherB16(SU + OFF_TY, 20, ntg * 8, k16 * 8, lane, bhi);
                gatherB16(SU + OFF_TY + 1280, 20, ntg * 8, k16 * 8, lane, blo);
                mma3(acc2[j], ahi, alo, bhi, blo);
            }
        }
        const int rlo = mt * 16 + (lane >> 2);
#pragma unroll
        for (int j = 0; j < 4; j++) {
            int c0 = (half * 4 + j) * 8 + 2 * (lane & 3);
            *(float2*)&SF[OFF_LT + rlo * 68 + c0]       = make_float2(acc2[j][0], acc2[j][1]);
            *(float2*)&SF[OFF_LT + (rlo + 8) * 68 + c0] = make_float2(acc2[j][2], acc2[j][3]);
        }
    } else if (wid < 12) {
        const int rb = wid - 8;
        float accg[4][4];
#pragma unroll
        for (int i = 0; i < 4; i++)
#pragma unroll
            for (int r = 0; r < 4; r++) accg[i][r] = 0.f;
#pragma unroll
        for (int k16 = 0; k16 < 2; k16++) {
            unsigned ahi[4], alo[4];
            gatherA16(SU + OFF_CQ, 20, rb * 16, k16 * 8, lane, ahi);
            gatherA16(SU + OFF_CQ + 1280, 20, rb * 16, k16 * 8, lane, alo);
#pragma unroll
            for (int nt = 0; nt < 4; nt++) {
                unsigned bhi[2], blo[2];
                gatherB16(SU + OFF_CHa, 20, rb * 16 + nt * 8, k16 * 8, lane, bhi);
                gatherB16(SU + OFF_CHa + 1600, 20, rb * 16 + nt * 8, k16 * 8, lane, blo);
                mma3(accg[nt], ahi, alo, bhi, blo);
            }
        }
        const int rlo = rb * 16 + (lane >> 2), rhi = rlo + 8;
#pragma unroll
        for (int nt = 0; nt < 4; nt++) {
            int m0 = rb * 16 + nt * 8 + 2 * (lane & 3);
            int k;
            k = m0 - rlo;     if (k >= 0 && k <= 16) SF[OFF_G + rlo * 21 + k] = accg[nt][0];
            k = m0 + 1 - rlo; if (k >= 0 && k <= 16) SF[OFF_G + rlo * 21 + k] = accg[nt][1];
            k = m0 - rhi;     if (k >= 0 && k <= 16) SF[OFF_G + rhi * 21 + k] = accg[nt][2];
            k = m0 + 1 - rhi; if (k >= 0 && k <= 16) SF[OFF_G + rhi * 21 + k] = accg[nt][3];
        }
    }
    __syncthreads();

    // ---------------- zero Wwin pool ----------------
    {
        uint4 z = make_uint4(0, 0, 0, 0);
        for (int i = tid; i < 1408; i += 512) ((uint4*)SU)[i] = z;
    }
    __syncthreads();

    // ---------------- softmax (4 rows per warp) ----------------
    {
        const float dt0 = SF[OFF_DT + lane];
        const float dt1 = SF[OFF_DT + lane + 32];
        for (int i = 0; i < 4; i++) {
            const int r = wid * 4 + i;
            const int l = l0 + r;
            const float uq_l = SF[OFF_UQ + r];

            float lt0 = leaky(uq_l + dt0 + SF[OFF_LT + r * 68 + lane]);
            float lt1 = leaky(uq_l + dt1 + SF[OFF_LT + r * 68 + 32 + lane]);

            const int ku = (lane <= 16) ? 0 : lane - 16;
            const int kd = (lane < 16) ? lane - 16 : 0;
            const bool ok = (l + kd >= 0) && (l + ku < Lq);
            const bool mk = ok && (SF[OFF_MK + r + ku] != 0.f);
            float lg = leaky(SF[OFF_UQ + r + ku] + SF[OFF_DS + r + kd + 16] + SF[OFF_G + r * 21 + ku]);
            float lw = mk ? lg : MASK_FILL;

            float lw2 = -INFINITY;
            if (lane == 0) {
                const bool ok2 = (l + 16 < Lq);
                const bool mk2 = ok2 && (SF[OFF_MK + r + 16] != 0.f);
                float lg2 = leaky(SF[OFF_UQ + r + 16] + SF[OFF_DS + r + 16] + SF[OFF_G + r * 21 + 16]);
                lw2 = mk2 ? lg2 : MASK_FILL;
            }

            float mx = fmaxf(fmaxf(lt0, lt1), lw);
            if (lane == 0) mx = fmaxf(mx, lw2);
#pragma unroll
            for (int o = 16; o; o >>= 1) mx = fmaxf(mx, __shfl_xor_sync(0xFFFFFFFFu, mx, o));
            float e0 = __expf(lt0 - mx), e1 = __expf(lt1 - mx), ew = __expf(lw - mx);
            float ew2 = (lane == 0) ? __expf(lw2 - mx) : 0.f;
            float sm = e0 + e1 + ew + ew2;
#pragma unroll
            for (int o = 16; o; o >>= 1) sm += __shfl_xor_sync(0xFFFFFFFFu, sm, o);
            const float inv = 1.0f / sm;

            store_split(SU + OFF_WT, SU + OFF_WT + 2304, r * 72 + lane,      e0 * inv);
            store_split(SU + OFF_WT, SU + OFF_WT + 2304, r * 72 + lane + 32, e1 * inv);

            float wwl = ew * inv;
            float wband = (lane <= 16) ? wwl : 0.f;
#pragma unroll
            for (int o = 16; o; o >>= 1) wband += __shfl_xor_sync(0xFFFFFFFFu, wband, o);
            if (lane == 0) {
                store_split(SU + OFF_WW, SU + OFF_WW + 2816, r * 88 + r,      wband);
                store_split(SU + OFF_WW, SU + OFF_WW + 2816, r * 88 + r + 16, ew2 * inv);
            } else if (lane >= 17) {
                store_split(SU + OFF_WW, SU + OFF_WW + 2816, r * 88 + r + (lane - 16), wwl);
            }
        }
    }
    __syncthreads();

    // ---------------- update (8 fat warps; window part band-limited) -----------
    if (wid < 8) {
        const int mt = wid >> 1;
        const int nthp = wid & 1;
        float acc[2][4] = {{0,0,0,0},{0,0,0,0}};
#pragma unroll
        for (int k16 = 0; k16 < 4; k16++) {
            unsigned ahi[4], alo[4];
            gatherA16(SU + OFF_WT, 36, mt * 16, k16 * 8, lane, ahi);
            gatherA16(SU + OFF_WT + 2304, 36, mt * 16, k16 * 8, lane, alo);
#pragma unroll
            for (int j = 0; j < 2; j++) {
                unsigned bhi[2], blo[2];
                gatherB16(SU + OFF_TT, 36, (nthp * 2 + j) * 8, k16 * 8, lane, bhi);
                gatherB16(SU + OFF_TT + 1152, 36, (nthp * 2 + j) * 8, k16 * 8, lane, blo);
                mma3(acc[j], ahi, alo, bhi, blo);
            }
        }
#pragma unroll
        for (int k16 = 0; k16 < 2; k16++) {
            const int KP0 = mt * 8 + k16 * 8;
            unsigned ahi[4], alo[4];
            gatherA16(SU + OFF_WW, 44, mt * 16, KP0, lane, ahi);
            gatherA16(SU + OFF_WW + 2816, 44, mt * 16, KP0, lane, alo);
#pragma unroll
            for (int j = 0; j < 2; j++) {
                unsigned bhi[2], blo[2];
                gatherB16(SU + OFF_CT, 44, (nthp * 2 + j) * 8, KP0, lane, bhi);
                gatherB16(SU + OFF_CT + 1408, 44, (nthp * 2 + j) * 8, KP0, lane, blo);
                mma3(acc[j], ahi, alo, bhi, blo);
            }
        }
        const int llo = l0 + mt * 16 + (lane >> 2);
#pragma unroll
        for (int j = 0; j < 2; j++) {
            const int col = n * 32 + (nthp * 2 + j) * 8 + 2 * (lane & 3);
            size_t g0 = (size_t)(b * Lq + llo) * Hq + col;
            size_t g1 = (size_t)(b * Lq + llo + 8) * Hq + col;
            float2 c0 = *(const float2*)&context[g0];
            float2 c1 = *(const float2*)&context[g1];
            *(float2*)&g_U[g0] = make_float2(acc[j][0] + c0.x, acc[j][1] + c0.y);
            *(float2*)&g_U[g1] = make_float2(acc[j][2] + c1.x, acc[j][3] + c1.y);
        }
    }
}

// ---------------- launch ----------------
extern "C" void kernel_launch(void* const* d_in, const int* in_sizes, int n_in,
                              void* d_out, int out_size)
{
    (void)in_sizes; (void)n_in; (void)out_size;
    const float* context   = (const float*)d_in[0];
    const float* types     = (const float*)d_in[1];
    const void*  cmask     = d_in[2];
    const float* W_types   = (const float*)d_in[3];
    const float* b_types   = (const float*)d_in[4];
    const float* W_context = (const float*)d_in[5];
    const float* b_context = (const float*)d_in[6];
    const float* upon      = (const float*)d_in[7];
    const float* down      = (const float*)d_in[8];
    const float* cross     = (const float*)d_in[9];
    const float* W_out     = (const float*)d_in[10];
    const float* b_out     = (const float*)d_in[11];
    float* out = (float*)d_out;

    float *p_types_h, *p_ch, *p_U;
    cudaGetSymbolAddress((void**)&p_types_h, g_types_h);
    cudaGetSymbolAddress((void**)&p_ch, g_ch);
    cudaGetSymbolAddress((void**)&p_U, g_U);

    cudaFuncSetAttribute(attn_mma6_kernel,
                         cudaFuncAttributeMaxDynamicSharedMemorySize, ATTN_SMEM_BYTES);

    prep_weights<<<dim3(8, 8, 3), 256>>>(W_types, W_context, W_out);
    prep_cross<<<1, 256>>>(cross);
    // types_h + fused dt
    gemm_bf16x3<<<dim3(4, 2), 256>>>(types, 0, b_types, p_types_h, 0, 2, upon, down);
    // context_h + fused uq/ds
    gemm_bf16x3<<<dim3(4, 128), 256>>>(context, 1, b_context, p_ch, 0, 1, upon, down);
    // pack ch/types into bf16x2 hi/lo operand copies
    pack_ops<<<dim3(17, 8, 4), 256>>>();
    // attention -> g_U = update + context
    attn_mma6_kernel<<<dim3(Lq / 64, NHq, Bq), 512, ATTN_SMEM_BYTES>>>(cmask, context);
    // out = tanh(g_U @ W_out + b_out)
    gemm_bf16x3<<<dim3(4, 128), 256>>>(p_U, 2, b_out, out, 1, 0, upon, down);
}

// round 13
// speedup vs baseline: 1.1753x; 1.1753x over previous
#include <cuda_runtime.h>
#include <cuda_bf16.h>
#include <math.h>

#define Bq 4
#define Lq 4096
#define Hq 256
#define NHq 8
#define Tq 64
#define Dq 32
#define WINq 16
#define NEG_SLOPE 5.0f
#define MASK_FILL -1e12f

// ---------------- scratch (device globals; no allocation allowed) ----------------
__device__ float g_types_h[Bq * Tq * Hq];
__device__ float g_ch[Bq * Lq * Hq];
__device__ float g_U[Bq * Lq * Hq];
__device__ float g_uq[Bq * NHq * Lq];
__device__ float g_ds[Bq * NHq * Lq];
__device__ float g_dt[Bq * NHq * Tq];
__device__ unsigned g_WtHi[3 * 256 * 128];
__device__ unsigned g_WtLo[3 * 256 * 128];

__device__ __forceinline__ float leaky(float x) { return x >= 0.f ? x : NEG_SLOPE * x; }

__device__ __forceinline__ unsigned pack_bf16x2(float lo_elem, float hi_elem) {
    unsigned r;
    asm("cvt.rn.bf16x2.f32 %0, %1, %2;" : "=r"(r) : "f"(hi_elem), "f"(lo_elem));
    return r;
}
__device__ __forceinline__ float bf_lo(unsigned p) { return __uint_as_float(p << 16); }
__device__ __forceinline__ float bf_hi(unsigned p) { return __uint_as_float(p & 0xFFFF0000u); }

__device__ __forceinline__ void mma16bf(float c[4], const unsigned a[4], const unsigned b[2]) {
    asm volatile(
        "mma.sync.aligned.m16n8k16.row.col.f32.bf16.bf16.f32 "
        "{%0,%1,%2,%3}, {%4,%5,%6,%7}, {%8,%9}, {%0,%1,%2,%3};"
        : "+f"(c[0]), "+f"(c[1]), "+f"(c[2]), "+f"(c[3])
        : "r"(a[0]), "r"(a[1]), "r"(a[2]), "r"(a[3]), "r"(b[0]), "r"(b[1]));
}
__device__ __forceinline__ void mma3(float c[4],
                                     const unsigned ahi[4], const unsigned alo[4],
                                     const unsigned bhi[2], const unsigned blo[2]) {
    mma16bf(c, ahi, bhi);
    mma16bf(c, ahi, blo);
    mma16bf(c, alo, bhi);
}

// ---- ldmatrix-based fragment loads (rows are 16B-aligned: strides 20/36/44 uints) ----
__device__ __forceinline__ void gatherA16(const unsigned* U, int stride,
                                          int R0, int KP0, int lane, unsigned a[4]) {
    int grp = lane >> 3, lr = lane & 7;
    int row = R0 + lr + ((grp & 1) << 3);
    int kp  = KP0 + ((grp >> 1) << 2);
    unsigned addr = (unsigned)__cvta_generic_to_shared(U + row * stride + kp);
    asm volatile("ldmatrix.sync.aligned.m8n8.x4.shared.b16 {%0,%1,%2,%3}, [%4];"
                 : "=r"(a[0]), "=r"(a[1]), "=r"(a[2]), "=r"(a[3]) : "r"(addr));
}
__device__ __forceinline__ void gatherB16(const unsigned* U, int stride,
                                          int N0, int KP0, int lane, unsigned bb[2]) {
    int grp = (lane >> 3) & 1, lr = lane & 7;
    int row = N0 + lr;
    int kp  = KP0 + (grp << 2);
    unsigned addr = (unsigned)__cvta_generic_to_shared(U + row * stride + kp);
    asm volatile("ldmatrix.sync.aligned.m8n8.x2.shared.b16 {%0,%1}, [%2];"
                 : "=r"(bb[0]), "=r"(bb[1]) : "r"(addr));
}

__device__ __forceinline__ void store_split(unsigned* baseHi, unsigned* baseLo,
                                            int halfIdx, float v) {
    __nv_bfloat16 h = __float2bfloat16(v);
    float r = v - __bfloat162float(h);
    ((__nv_bfloat16*)baseHi)[halfIdx] = h;
    ((__nv_bfloat16*)baseLo)[halfIdx] = __float2bfloat16(r);
}

__device__ __forceinline__ int mask_mode(const void* m) {
    unsigned u = *(const unsigned*)m;
    if (u == 0x01010101u) return 0;
    if (u == 0x3F800000u) return 2;
    return 1;
}
__device__ __forceinline__ bool mask_at(const void* m, int mode, long idx) {
    if (mode == 0) return ((const unsigned char*)m)[idx] != 0;
    if (mode == 1) return ((const int*)m)[idx] != 0;
    return ((const float*)m)[idx] != 0.f;
}

// ---------------- prep: transpose + bf16-split the three 256x256 weights -------
__global__ __launch_bounds__(256) void prep_weights(
    const float* __restrict__ W0, const float* __restrict__ W1,
    const float* __restrict__ W2)
{
    __shared__ float s[32][33];
    const int w = blockIdx.z;
    const float* W = (w == 0) ? W0 : (w == 1) ? W1 : W2;
    const int k0 = blockIdx.x * 32, n0 = blockIdx.y * 32;
    const int tid = threadIdx.x;
#pragma unroll
    for (int it = 0; it < 4; it++) {
        int idx = it * 256 + tid;
        int kr = idx >> 5, nc = idx & 31;
        s[kr][nc] = W[(size_t)(k0 + kr) * 256 + n0 + nc];
    }
    __syncthreads();
#pragma unroll
    for (int it = 0; it < 2; it++) {
        int idx = it * 256 + tid;
        int nn = idx >> 4, kp = idx & 15;
        float e0 = s[2 * kp][nn], e1 = s[2 * kp + 1][nn];
        unsigned hi = pack_bf16x2(e0, e1);
        unsigned lo = pack_bf16x2(e0 - bf_lo(hi), e1 - bf_hi(hi));
        size_t o = (size_t)(w * 256 + n0 + nn) * 128 + (k0 >> 1) + kp;
        g_WtHi[o] = hi;
        g_WtLo[o] = lo;
    }
}

// ---------------- bf16x3 GEMM + fused row-dot epilogue --------------------------
// mode: 0 = plain (+tanh per flag), 1 = also uq/ds (rows are b*L+l), 2 = dt
__global__ __launch_bounds__(256) void gemm_bf16x3(
    const float* __restrict__ A, int wsel,
    const float* __restrict__ bias, float* __restrict__ C,
    int dotanh, int mode,
    const float* __restrict__ upon, const float* __restrict__ down)
{
    __shared__ unsigned sAhi[128 * 20];
    __shared__ unsigned sAlo[128 * 20];
    __shared__ unsigned sBhi[64 * 20];
    __shared__ unsigned sBlo[64 * 20];

    const int tid = threadIdx.x;
    const int wid = tid >> 5, lane = tid & 31;
    const int wm = wid >> 1, wn = wid & 1;
    const int bm = blockIdx.y * 128;
    const int bn = blockIdx.x * 64;
    const unsigned* WHi = g_WtHi + (size_t)wsel * 256 * 128;
    const unsigned* WLo = g_WtLo + (size_t)wsel * 256 * 128;

    float acc[2][4][4];
#pragma unroll
    for (int mt = 0; mt < 2; mt++)
#pragma unroll
        for (int nt = 0; nt < 4; nt++)
#pragma unroll
            for (int r = 0; r < 4; r++) acc[mt][nt][r] = 0.f;

    for (int chunk = 0; chunk < 8; chunk++) {
        const int kc0 = chunk * 32;
#pragma unroll
        for (int i = 0; i < 4; i++) {
            int fidx = i * 256 + tid;
            int row = fidx >> 3, col4 = fidx & 7;
            float4 v = *(const float4*)(A + (size_t)(bm + row) * 256 + kc0 + col4 * 4);
            unsigned h0 = pack_bf16x2(v.x, v.y);
            unsigned h1 = pack_bf16x2(v.z, v.w);
            unsigned l0 = pack_bf16x2(v.x - bf_lo(h0), v.y - bf_hi(h0));
            unsigned l1 = pack_bf16x2(v.z - bf_lo(h1), v.w - bf_hi(h1));
            int o = row * 20 + col4 * 2;
            *(uint2*)&sAhi[o] = make_uint2(h0, h1);
            *(uint2*)&sAlo[o] = make_uint2(l0, l1);
        }
#pragma unroll
        for (int i = 0; i < 2; i++) {
            int fidx = i * 256 + tid;
            int row = fidx >> 3, j = fidx & 7;
            size_t src = (size_t)(bn + row) * 128 + (kc0 >> 1) + j * 2;
            int o = row * 20 + j * 2;
            *(uint2*)&sBhi[o] = *(const uint2*)&WHi[src];
            *(uint2*)&sBlo[o] = *(const uint2*)&WLo[src];
        }
        __syncthreads();
#pragma unroll
        for (int k16 = 0; k16 < 2; k16++) {
            unsigned ahi[2][4], alo[2][4];
#pragma unroll
            for (int mt = 0; mt < 2; mt++) {
                gatherA16(sAhi, 20, wm * 32 + mt * 16, k16 * 8, lane, ahi[mt]);
                gatherA16(sAlo, 20, wm * 32 + mt * 16, k16 * 8, lane, alo[mt]);
            }
#pragma unroll
            for (int nt = 0; nt < 4; nt++) {
                unsigned bhi[2], blo[2];
                gatherB16(sBhi, 20, wn * 32 + nt * 8, k16 * 8, lane, bhi);
                gatherB16(sBlo, 20, wn * 32 + nt * 8, k16 * 8, lane, blo);
#pragma unroll
                for (int mt = 0; mt < 2; mt++) {
                    mma16bf(acc[mt][nt], ahi[mt], bhi);
                    mma16bf(acc[mt][nt], ahi[mt], blo);
                    mma16bf(acc[mt][nt], alo[mt], bhi);
                }
            }
        }
        __syncthreads();
    }

    const int row0 = bm + wm * 32 + (lane >> 2);
    const int col0 = bn + wn * 32 + (lane & 3) * 2;
    float pa[4] = {0.f, 0.f, 0.f, 0.f};
    float pd[4] = {0.f, 0.f, 0.f, 0.f};
#pragma unroll
    for (int mt = 0; mt < 2; mt++)
#pragma unroll
        for (int nt = 0; nt < 4; nt++) {
            int r = row0 + mt * 16;
            int c = col0 + nt * 8;
            float b0 = bias[c], b1 = bias[c + 1];
            float v00 = acc[mt][nt][0] + b0, v01 = acc[mt][nt][1] + b1;
            float v10 = acc[mt][nt][2] + b0, v11 = acc[mt][nt][3] + b1;
            if (mode == 1) {
                float u0 = upon[c], u1 = upon[c + 1];
                float d0 = down[c], d1 = down[c + 1];
                pa[mt * 2 + 0] += v00 * u0 + v01 * u1;
                pa[mt * 2 + 1] += v10 * u0 + v11 * u1;
                pd[mt * 2 + 0] += v00 * d0 + v01 * d1;
                pd[mt * 2 + 1] += v10 * d0 + v11 * d1;
            } else if (mode == 2) {
                float d0 = down[c], d1 = down[c + 1];
                pd[mt * 2 + 0] += v00 * d0 + v01 * d1;
                pd[mt * 2 + 1] += v10 * d0 + v11 * d1;
            }
            float2 o0 = make_float2(v00, v01);
            float2 o1 = make_float2(v10, v11);
            if (dotanh) {
                o0.x = tanhf(o0.x); o0.y = tanhf(o0.y);
                o1.x = tanhf(o1.x); o1.y = tanhf(o1.y);
            }
            *(float2*)(C + (size_t)r * 256 + c)       = o0;
            *(float2*)(C + (size_t)(r + 8) * 256 + c) = o1;
        }

    if (mode) {
#pragma unroll
        for (int j = 0; j < 4; j++) {
            pa[j] += __shfl_xor_sync(0xFFFFFFFFu, pa[j], 1);
            pa[j] += __shfl_xor_sync(0xFFFFFFFFu, pa[j], 2);
            pd[j] += __shfl_xor_sync(0xFFFFFFFFu, pd[j], 1);
            pd[j] += __shfl_xor_sync(0xFFFFFFFFu, pd[j], 2);
        }
        if ((lane & 3) == 0) {
            const int hn = (bn >> 5) + wn;
#pragma unroll
            for (int j = 0; j < 4; j++) {
                int row = row0 + (j >> 1) * 16 + (j & 1) * 8;
                if (mode == 1) {
                    int b = row >> 12, l = row & 4095;
                    g_uq[((size_t)(b * NHq + hn)) * Lq + l] = pa[j];
                    g_ds[((size_t)(b * NHq + hn)) * Lq + l] = pd[j];
                } else {
                    int b = row >> 6, t = row & 63;
                    g_dt[(b * NHq + hn) * Tq + t] = pd[j];
                }
            }
        }
    }
}

// ---------------- attention core v5 (R10) with LDSM fragment loads --------------
#define OFF_XT    0
#define OFF_CHa   1280
#define OFF_TY    4480
#define OFF_CQ    7040
#define OFF_WW    0
#define OFF_WT    5632
#define OFF_TT    10240
#define OFF_CT    12544
#define OFF_LT    15360
#define OFF_G     19712
#define OFF_UQ    21056
#define OFF_DS    21136
#define OFF_MK    21216
#define OFF_DT    21296
#define SMEM_UINTS 21360
#define ATTN_SMEM_BYTES (SMEM_UINTS * 4)

__global__ __launch_bounds__(512, 2) void attn_mma5_kernel(
    const float* __restrict__ cross, const void* __restrict__ maskp,
    const float* __restrict__ context)
{
    extern __shared__ unsigned SU[];
    float* SF = (float*)SU;
    const int tid = threadIdx.x, wid = tid >> 5, lane = tid & 31;
    const int n = blockIdx.y, b = blockIdx.z;
    const int l0 = blockIdx.x * 64;
    const int mmode = mask_mode(maskp);
    const int bnL = (b * NHq + n) * Lq;
    const long maskbase = (long)b * Lq;

    // ---------------- stage row-major (packed 32-bit stores) ----------------
    {
        const int j2 = lane & 15, rs = lane >> 4;
#pragma unroll
        for (int it = 0; it < 2; it++) {
            int t = it * 32 + wid * 2 + rs;
            float2 v = *(const float2*)(g_types_h + (size_t)(b * Tq + t) * Hq + n * 32 + 2 * j2);
            unsigned hi = pack_bf16x2(v.x, v.y);
            unsigned lo = pack_bf16x2(v.x - bf_lo(hi), v.y - bf_hi(hi));
            SU[OFF_TY + t * 20 + j2] = hi;
            SU[OFF_TY + 1280 + t * 20 + j2] = lo;
        }
        for (int r = wid * 2 + rs; r < 80; r += 32) {
            int row = l0 + r; if (row > Lq - 1) row = Lq - 1;
            float2 v = *(const float2*)(g_ch + (size_t)(b * Lq + row) * Hq + n * 32 + 2 * j2);
            unsigned hi = pack_bf16x2(v.x, v.y);
            unsigned lo = pack_bf16x2(v.x - bf_lo(hi), v.y - bf_hi(hi));
            SU[OFF_CHa + r * 20 + j2] = hi;
            SU[OFF_CHa + 1600 + r * 20 + j2] = lo;
        }
    }
    for (int d = wid; d < 32; d += 16) {
        float v = cross[(size_t)(n * Dq + d) * Dq + lane];
        store_split(SU + OFF_XT, SU + OFF_XT + 640, lane * 40 + d, v);
    }
    for (int i = tid; i < 80; i += 512) {
        int ru = l0 + i; if (ru > Lq - 1) ru = Lq - 1;
        SF[OFF_UQ + i] = g_uq[bnL + ru];
        SF[OFF_MK + i] = mask_at(maskp, mmode, maskbase + ru) ? 1.f : 0.f;
        int rd = l0 + i - 16; if (rd < 0) rd = 0;
        SF[OFF_DS + i] = g_ds[bnL + rd];
    }
    for (int i = tid; i < 64; i += 512) SF[OFF_DT + i] = g_dt[(b * NHq + n) * Tq + i];
    __syncthreads();

    // ---------------- build typesT / CHT from packed row-major arrays ---------
    {
        const int dd = ((wid & 3) << 3) + (lane >> 2);
        const int kpb = ((wid >> 2) << 2) + (lane & 3);
        const unsigned sel = (dd & 1) ? 0x7632u : 0x5410u;
#pragma unroll
        for (int it = 0; it < 2; it++) {
            int kp = kpb + it * 16;
            int u0 = OFF_TY + kp * 40 + (dd >> 1);
            unsigned ph = __byte_perm(SU[u0], SU[u0 + 20], sel);
            unsigned pl = __byte_perm(SU[u0 + 1280], SU[u0 + 1280 + 20], sel);
            SU[OFF_TT + dd * 36 + kp] = ph;
            SU[OFF_TT + 1152 + dd * 36 + kp] = pl;
        }
#pragma unroll
        for (int it = 0; it < 3; it++) {
            int kp = kpb + it * 16;
            if (kp < 40) {
                int u0 = OFF_CHa + kp * 40 + (dd >> 1);
                unsigned ph = __byte_perm(SU[u0], SU[u0 + 20], sel);
                unsigned pl = __byte_perm(SU[u0 + 1600], SU[u0 + 1600 + 20], sel);
                SU[OFF_CT + dd * 44 + kp] = ph;
                SU[OFF_CT + 1408 + dd * 44 + kp] = pl;
            }
        }
    }
    __syncthreads();

    // ---------------- phase A: CQ(64x32) = CH @ crossT (16 warps) ----------------
    {
        const int mt = wid >> 2, nh = wid & 3;
        float acc[4] = {0, 0, 0, 0};
#pragma unroll
        for (int k16 = 0; k16 < 2; k16++) {
            unsigned ahi[4], alo[4];
            gatherA16(SU + OFF_CHa, 20, mt * 16, k16 * 8, lane, ahi);
            gatherA16(SU + OFF_CHa + 1600, 20, mt * 16, k16 * 8, lane, alo);
            unsigned bhi[2], blo[2];
            gatherB16(SU + OFF_XT, 20, nh * 8, k16 * 8, lane, bhi);
            gatherB16(SU + OFF_XT + 640, 20, nh * 8, k16 * 8, lane, blo);
            mma3(acc, ahi, alo, bhi, blo);
        }
        const int rlo = mt * 16 + (lane >> 2);
        const int cp = nh * 4 + (lane & 3);
        unsigned h0 = pack_bf16x2(acc[0], acc[1]);
        unsigned l0p = pack_bf16x2(acc[0] - bf_lo(h0), acc[1] - bf_hi(h0));
        unsigned h1 = pack_bf16x2(acc[2], acc[3]);
        unsigned l1p = pack_bf16x2(acc[2] - bf_lo(h1), acc[3] - bf_hi(h1));
        SU[OFF_CQ + rlo * 20 + cp]              = h0;
        SU[OFF_CQ + 1280 + rlo * 20 + cp]       = l0p;
        SU[OFF_CQ + (rlo + 8) * 20 + cp]        = h1;
        SU[OFF_CQ + 1280 + (rlo + 8) * 20 + cp] = l1p;
    }
    __syncthreads();

    // ---------------- phase B ----------------
    if (wid < 8) {     // logitsT
        const int mt = wid >> 1, half = wid & 1;
        float acc2[4][4];
#pragma unroll
        for (int i = 0; i < 4; i++)
#pragma unroll
            for (int r = 0; r < 4; r++) acc2[i][r] = 0.f;
#pragma unroll
        for (int k16 = 0; k16 < 2; k16++) {
            unsigned ahi[4], alo[4];
            gatherA16(SU + OFF_CQ, 20, mt * 16, k16 * 8, lane, ahi);
            gatherA16(SU + OFF_CQ + 1280, 20, mt * 16, k16 * 8, lane, alo);
#pragma unroll
            for (int j = 0; j < 4; j++) {
                int ntg = half * 4 + j;
                unsigned bhi[2], blo[2];
                gatherB16(SU + OFF_TY, 20, ntg * 8, k16 * 8, lane, bhi);
                gatherB16(SU + OFF_TY + 1280, 20, ntg * 8, k16 * 8, lane, blo);
                mma3(acc2[j], ahi, alo, bhi, blo);
            }
        }
        const int rlo = mt * 16 + (lane >> 2);
#pragma unroll
        for (int j = 0; j < 4; j++) {
            int c0 = (half * 4 + j) * 8 + 2 * (lane & 3);
            *(float2*)&SF[OFF_LT + rlo * 68 + c0]       = make_float2(acc2[j][0], acc2[j][1]);
            *(float2*)&SF[OFF_LT + (rlo + 8) * 68 + c0] = make_float2(acc2[j][2], acc2[j][3]);
        }
    } else {           // band G
        const int w = wid - 8;
        const int rb = w >> 1, half = w & 1;
        float accg[2][4];
#pragma unroll
        for (int i = 0; i < 2; i++)
#pragma unroll
            for (int r = 0; r < 4; r++) accg[i][r] = 0.f;
#pragma unroll
        for (int k16 = 0; k16 < 2; k16++) {
            unsigned ahi[4], alo[4];
            gatherA16(SU + OFF_CQ, 20, rb * 16, k16 * 8, lane, ahi);
            gatherA16(SU + OFF_CQ + 1280, 20, rb * 16, k16 * 8, lane, alo);
#pragma unroll
            for (int j = 0; j < 2; j++) {
                int nt = half * 2 + j;
                unsigned bhi[2], blo[2];
                gatherB16(SU + OFF_CHa, 20, rb * 16 + nt * 8, k16 * 8, lane, bhi);
                gatherB16(SU + OFF_CHa + 1600, 20, rb * 16 + nt * 8, k16 * 8, lane, blo);
                mma3(accg[j], ahi, alo, bhi, blo);
            }
        }
        const int rlo = rb * 16 + (lane >> 2), rhi = rlo + 8;
#pragma unroll
        for (int j = 0; j < 2; j++) {
            int m0 = rb * 16 + (half * 2 + j) * 8 + 2 * (lane & 3);
            int k;
            k = m0 - rlo;     if (k >= 0 && k <= 16) SF[OFF_G + rlo * 21 + k] = accg[j][0];
            k = m0 + 1 - rlo; if (k >= 0 && k <= 16) SF[OFF_G + rlo * 21 + k] = accg[j][1];
            k = m0 - rhi;     if (k >= 0 && k <= 16) SF[OFF_G + rhi * 21 + k] = accg[j][2];
            k = m0 + 1 - rhi; if (k >= 0 && k <= 16) SF[OFF_G + rhi * 21 + k] = accg[j][3];
        }
    }
    __syncthreads();

    // ---------------- zero Wwin pool only ----------------
    {
        uint4 z = make_uint4(0, 0, 0, 0);
        for (int i = tid; i < 1408; i += 512) ((uint4*)SU)[i] = z;
    }
    __syncthreads();

    // ---------------- softmax (4 rows per warp) ----------------
    for (int i = 0; i < 4; i++) {
        const int r = wid * 4 + i;
        const int l = l0 + r;
        const float uq_l = SF[OFF_UQ + r];

        float lt0 = leaky(uq_l + SF[OFF_DT + lane]      + SF[OFF_LT + r * 68 + lane]);
        float lt1 = leaky(uq_l + SF[OFF_DT + lane + 32] + SF[OFF_LT + r * 68 + 32 + lane]);

        const int ku = (lane <= 16) ? 0 : lane - 16;
        const int kd = (lane < 16) ? lane - 16 : 0;
        const bool ok = (l + kd >= 0) && (l + ku < Lq);
        const bool mk = ok && (SF[OFF_MK + r + ku] != 0.f);
        float lg = leaky(SF[OFF_UQ + r + ku] + SF[OFF_DS + r + kd + 16] + SF[OFF_G + r * 21 + ku]);
        float lw = mk ? lg : MASK_FILL;

        float lw2 = -INFINITY;
        if (lane == 0) {
            const bool ok2 = (l + 16 < Lq);
            const bool mk2 = ok2 && (SF[OFF_MK + r + 16] != 0.f);
            float lg2 = leaky(SF[OFF_UQ + r + 16] + SF[OFF_DS + r + 16] + SF[OFF_G + r * 21 + 16]);
            lw2 = mk2 ? lg2 : MASK_FILL;
        }

        float mx = fmaxf(fmaxf(lt0, lt1), lw);
        if (lane == 0) mx = fmaxf(mx, lw2);
#pragma unroll
        for (int o = 16; o; o >>= 1) mx = fmaxf(mx, __shfl_xor_sync(0xFFFFFFFFu, mx, o));
        float e0 = __expf(lt0 - mx), e1 = __expf(lt1 - mx), ew = __expf(lw - mx);
        float ew2 = (lane == 0) ? __expf(lw2 - mx) : 0.f;
        float sm = e0 + e1 + ew + ew2;
#pragma unroll
        for (int o = 16; o; o >>= 1) sm += __shfl_xor_sync(0xFFFFFFFFu, sm, o);
        const float inv = 1.0f / sm;

        store_split(SU + OFF_WT, SU + OFF_WT + 2304, r * 72 + lane,      e0 * inv);
        store_split(SU + OFF_WT, SU + OFF_WT + 2304, r * 72 + lane + 32, e1 * inv);

        float wwl = ew * inv;
        float wband = (lane <= 16) ? wwl : 0.f;
#pragma unroll
        for (int o = 16; o; o >>= 1) wband += __shfl_xor_sync(0xFFFFFFFFu, wband, o);
        if (lane == 0) {
            store_split(SU + OFF_WW, SU + OFF_WW + 2816, r * 88 + r,      wband);
            store_split(SU + OFF_WW, SU + OFF_WW + 2816, r * 88 + r + 16, ew2 * inv);
        } else if (lane >= 17) {
            store_split(SU + OFF_WW, SU + OFF_WW + 2816, r * 88 + r + (lane - 16), wwl);
        }
    }
    __syncthreads();

    // ---------------- update (16 warps; window part band-limited to K=32) ------
    {
        const int mt = wid & 3;
        const int nth = wid >> 2;
        float acc[4] = {0, 0, 0, 0};
#pragma unroll
        for (int k16 = 0; k16 < 4; k16++) {
            unsigned ahi[4], alo[4];
            gatherA16(SU + OFF_WT, 36, mt * 16, k16 * 8, lane, ahi);
            gatherA16(SU + OFF_WT + 2304, 36, mt * 16, k16 * 8, lane, alo);
            unsigned bhi[2], blo[2];
            gatherB16(SU + OFF_TT, 36, nth * 8, k16 * 8, lane, bhi);
            gatherB16(SU + OFF_TT + 1152, 36, nth * 8, k16 * 8, lane, blo);
            mma3(acc, ahi, alo, bhi, blo);
        }
#pragma unroll
        for (int k16 = 0; k16 < 2; k16++) {   // band: kpairs [mt*8, mt*8+16)
            const int KP0 = mt * 8 + k16 * 8;
            unsigned ahi[4], alo[4];
            gatherA16(SU + OFF_WW, 44, mt * 16, KP0, lane, ahi);
            gatherA16(SU + OFF_WW + 2816, 44, mt * 16, KP0, lane, alo);
            unsigned bhi[2], blo[2];
            gatherB16(SU + OFF_CT, 44, nth * 8, KP0, lane, bhi);
            gatherB16(SU + OFF_CT + 1408, 44, nth * 8, KP0, lane, blo);
            mma3(acc, ahi, alo, bhi, blo);
        }
        const int llo = l0 + mt * 16 + (lane >> 2);
        const int col = n * 32 + nth * 8 + 2 * (lane & 3);
        size_t g0 = (size_t)(b * Lq + llo) * Hq + col;
        size_t g1 = (size_t)(b * Lq + llo + 8) * Hq + col;
        float2 c0 = *(const float2*)&context[g0];
        float2 c1 = *(const float2*)&context[g1];
        *(float2*)&g_U[g0] = make_float2(acc[0] + c0.x, acc[1] + c0.y);
        *(float2*)&g_U[g1] = make_float2(acc[2] + c1.x, acc[3] + c1.y);
    }
}

// ---------------- launch ----------------
extern "C" void kernel_launch(void* const* d_in, const int* in_sizes, int n_in,
                              void* d_out, int out_size)
{
    (void)in_sizes; (void)n_in; (void)out_size;
    const float* context   = (const float*)d_in[0];
    const float* types     = (const float*)d_in[1];
    const void*  cmask     = d_in[2];
    const float* W_types   = (const float*)d_in[3];
    const float* b_types   = (const float*)d_in[4];
    const float* W_context = (const float*)d_in[5];
    const float* b_context = (const float*)d_in[6];
    const float* upon      = (const float*)d_in[7];
    const float* down      = (const float*)d_in[8];
    const float* cross     = (const float*)d_in[9];
    const float* W_out     = (const float*)d_in[10];
    const float* b_out     = (const float*)d_in[11];
    float* out = (float*)d_out;

    float *p_types_h, *p_ch, *p_U;
    cudaGetSymbolAddress((void**)&p_types_h, g_types_h);
    cudaGetSymbolAddress((void**)&p_ch, g_ch);
    cudaGetSymbolAddress((void**)&p_U, g_U);

    cudaFuncSetAttribute(attn_mma5_kernel,
                         cudaFuncAttributeMaxDynamicSharedMemorySize, ATTN_SMEM_BYTES);

    prep_weights<<<dim3(8, 8, 3), 256>>>(W_types, W_context, W_out);
    gemm_bf16x3<<<dim3(4, 2), 256>>>(types, 0, b_types, p_types_h, 0, 2, upon, down);
    gemm_bf16x3<<<dim3(4, 128), 256>>>(context, 1, b_context, p_ch, 0, 1, upon, down);
    attn_mma5_kernel<<<dim3(Lq / 64, NHq, Bq), 512, ATTN_SMEM_BYTES>>>(cross, cmask, context);
    gemm_bf16x3<<<dim3(4, 128), 256>>>(p_U, 2, b_out, out, 1, 0, upon, down);
}

// round 14
// speedup vs baseline: 1.3710x; 1.1665x over previous
#include <cuda_runtime.h>
#include <cuda_bf16.h>
#include <cuda_fp16.h>
#include <math.h>

#define Bq 4
#define Lq 4096
#define Hq 256
#define NHq 8
#define Tq 64
#define Dq 32
#define WINq 16
#define NEG_SLOPE 5.0f
#define MASK_FILL -1e12f

// ---------------- scratch (device globals; no allocation allowed) ----------------
__device__ float g_types_h[Bq * Tq * Hq];
__device__ float g_ch[Bq * Lq * Hq];
__device__ float g_U[Bq * Lq * Hq];
__device__ float g_uq[Bq * NHq * Lq];
__device__ float g_ds[Bq * NHq * Lq];
__device__ float g_dt[Bq * NHq * Tq];
__device__ unsigned g_WtHi[3 * 256 * 128];
__device__ unsigned g_WtLo[3 * 256 * 128];

__device__ __forceinline__ float leaky(float x) { return x >= 0.f ? x : NEG_SLOPE * x; }

__device__ __forceinline__ unsigned pack_bf16x2(float lo_elem, float hi_elem) {
    unsigned r;
    asm("cvt.rn.bf16x2.f32 %0, %1, %2;" : "=r"(r) : "f"(hi_elem), "f"(lo_elem));
    return r;
}
__device__ __forceinline__ float bf_lo(unsigned p) { return __uint_as_float(p << 16); }
__device__ __forceinline__ float bf_hi(unsigned p) { return __uint_as_float(p & 0xFFFF0000u); }

__device__ __forceinline__ unsigned pack_f16x2(float lo_elem, float hi_elem) {
    unsigned r;
    asm("cvt.rn.f16x2.f32 %0, %1, %2;" : "=r"(r) : "f"(hi_elem), "f"(lo_elem));
    return r;
}

__device__ __forceinline__ void mma16bf(float c[4], const unsigned a[4], const unsigned b[2]) {
    asm volatile(
        "mma.sync.aligned.m16n8k16.row.col.f32.bf16.bf16.f32 "
        "{%0,%1,%2,%3}, {%4,%5,%6,%7}, {%8,%9}, {%0,%1,%2,%3};"
        : "+f"(c[0]), "+f"(c[1]), "+f"(c[2]), "+f"(c[3])
        : "r"(a[0]), "r"(a[1]), "r"(a[2]), "r"(a[3]), "r"(b[0]), "r"(b[1]));
}
__device__ __forceinline__ void mma16f(float c[4], const unsigned a[4], const unsigned b[2]) {
    asm volatile(
        "mma.sync.aligned.m16n8k16.row.col.f32.f16.f16.f32 "
        "{%0,%1,%2,%3}, {%4,%5,%6,%7}, {%8,%9}, {%0,%1,%2,%3};"
        : "+f"(c[0]), "+f"(c[1]), "+f"(c[2]), "+f"(c[3])
        : "r"(a[0]), "r"(a[1]), "r"(a[2]), "r"(a[3]), "r"(b[0]), "r"(b[1]));
}

// ---- ldmatrix-based fragment loads (rows 16B-aligned: strides 20/36/44 uints) ----
__device__ __forceinline__ void gatherA16(const unsigned* U, int stride,
                                          int R0, int KP0, int lane, unsigned a[4]) {
    int grp = lane >> 3, lr = lane & 7;
    int row = R0 + lr + ((grp & 1) << 3);
    int kp  = KP0 + ((grp >> 1) << 2);
    unsigned addr = (unsigned)__cvta_generic_to_shared(U + row * stride + kp);
    asm volatile("ldmatrix.sync.aligned.m8n8.x4.shared.b16 {%0,%1,%2,%3}, [%4];"
                 : "=r"(a[0]), "=r"(a[1]), "=r"(a[2]), "=r"(a[3]) : "r"(addr));
}
__device__ __forceinline__ void gatherB16(const unsigned* U, int stride,
                                          int N0, int KP0, int lane, unsigned bb[2]) {
    int grp = (lane >> 3) & 1, lr = lane & 7;
    int row = N0 + lr;
    int kp  = KP0 + (grp << 2);
    unsigned addr = (unsigned)__cvta_generic_to_shared(U + row * stride + kp);
    asm volatile("ldmatrix.sync.aligned.m8n8.x2.shared.b16 {%0,%1}, [%2];"
                 : "=r"(bb[0]), "=r"(bb[1]) : "r"(addr));
}

__device__ __forceinline__ int mask_mode(const void* m) {
    unsigned u = *(const unsigned*)m;
    if (u == 0x01010101u) return 0;
    if (u == 0x3F800000u) return 2;
    return 1;
}
__device__ __forceinline__ bool mask_at(const void* m, int mode, long idx) {
    if (mode == 0) return ((const unsigned char*)m)[idx] != 0;
    if (mode == 1) return ((const int*)m)[idx] != 0;
    return ((const float*)m)[idx] != 0.f;
}

// ---------------- prep: transpose + bf16-split the three 256x256 weights -------
__global__ __launch_bounds__(256) void prep_weights(
    const float* __restrict__ W0, const float* __restrict__ W1,
    const float* __restrict__ W2)
{
    __shared__ float s[32][33];
    const int w = blockIdx.z;
    const float* W = (w == 0) ? W0 : (w == 1) ? W1 : W2;
    const int k0 = blockIdx.x * 32, n0 = blockIdx.y * 32;
    const int tid = threadIdx.x;
#pragma unroll
    for (int it = 0; it < 4; it++) {
        int idx = it * 256 + tid;
        int kr = idx >> 5, nc = idx & 31;
        s[kr][nc] = W[(size_t)(k0 + kr) * 256 + n0 + nc];
    }
    __syncthreads();
#pragma unroll
    for (int it = 0; it < 2; it++) {
        int idx = it * 256 + tid;
        int nn = idx >> 4, kp = idx & 15;
        float e0 = s[2 * kp][nn], e1 = s[2 * kp + 1][nn];
        unsigned hi = pack_bf16x2(e0, e1);
        unsigned lo = pack_bf16x2(e0 - bf_lo(hi), e1 - bf_hi(hi));
        size_t o = (size_t)(w * 256 + n0 + nn) * 128 + (k0 >> 1) + kp;
        g_WtHi[o] = hi;
        g_WtLo[o] = lo;
    }
}

// ---------------- bf16x3 GEMM + fused row-dot epilogue --------------------------
__global__ __launch_bounds__(256) void gemm_bf16x3(
    const float* __restrict__ A, int wsel,
    const float* __restrict__ bias, float* __restrict__ C,
    int dotanh, int mode,
    const float* __restrict__ upon, const float* __restrict__ down)
{
    __shared__ unsigned sAhi[128 * 20];
    __shared__ unsigned sAlo[128 * 20];
    __shared__ unsigned sBhi[64 * 20];
    __shared__ unsigned sBlo[64 * 20];

    const int tid = threadIdx.x;
    const int wid = tid >> 5, lane = tid & 31;
    const int wm = wid >> 1, wn = wid & 1;
    const int bm = blockIdx.y * 128;
    const int bn = blockIdx.x * 64;
    const unsigned* WHi = g_WtHi + (size_t)wsel * 256 * 128;
    const unsigned* WLo = g_WtLo + (size_t)wsel * 256 * 128;

    float acc[2][4][4];
#pragma unroll
    for (int mt = 0; mt < 2; mt++)
#pragma unroll
        for (int nt = 0; nt < 4; nt++)
#pragma unroll
            for (int r = 0; r < 4; r++) acc[mt][nt][r] = 0.f;

    for (int chunk = 0; chunk < 8; chunk++) {
        const int kc0 = chunk * 32;
#pragma unroll
        for (int i = 0; i < 4; i++) {
            int fidx = i * 256 + tid;
            int row = fidx >> 3, col4 = fidx & 7;
            float4 v = *(const float4*)(A + (size_t)(bm + row) * 256 + kc0 + col4 * 4);
            unsigned h0 = pack_bf16x2(v.x, v.y);
            unsigned h1 = pack_bf16x2(v.z, v.w);
            unsigned l0 = pack_bf16x2(v.x - bf_lo(h0), v.y - bf_hi(h0));
            unsigned l1 = pack_bf16x2(v.z - bf_lo(h1), v.w - bf_hi(h1));
            int o = row * 20 + col4 * 2;
            *(uint2*)&sAhi[o] = make_uint2(h0, h1);
            *(uint2*)&sAlo[o] = make_uint2(l0, l1);
        }
#pragma unroll
        for (int i = 0; i < 2; i++) {
            int fidx = i * 256 + tid;
            int row = fidx >> 3, j = fidx & 7;
            size_t src = (size_t)(bn + row) * 128 + (kc0 >> 1) + j * 2;
            int o = row * 20 + j * 2;
            *(uint2*)&sBhi[o] = *(const uint2*)&WHi[src];
            *(uint2*)&sBlo[o] = *(const uint2*)&WLo[src];
        }
        __syncthreads();
#pragma unroll
        for (int k16 = 0; k16 < 2; k16++) {
            unsigned ahi[2][4], alo[2][4];
#pragma unroll
            for (int mt = 0; mt < 2; mt++) {
                gatherA16(sAhi, 20, wm * 32 + mt * 16, k16 * 8, lane, ahi[mt]);
                gatherA16(sAlo, 20, wm * 32 + mt * 16, k16 * 8, lane, alo[mt]);
            }
#pragma unroll
            for (int nt = 0; nt < 4; nt++) {
                unsigned bhi[2], blo[2];
                gatherB16(sBhi, 20, wn * 32 + nt * 8, k16 * 8, lane, bhi);
                gatherB16(sBlo, 20, wn * 32 + nt * 8, k16 * 8, lane, blo);
#pragma unroll
                for (int mt = 0; mt < 2; mt++) {
                    mma16bf(acc[mt][nt], ahi[mt], bhi);
                    mma16bf(acc[mt][nt], ahi[mt], blo);
                    mma16bf(acc[mt][nt], alo[mt], bhi);
                }
            }
        }
        __syncthreads();
    }

    const int row0 = bm + wm * 32 + (lane >> 2);
    const int col0 = bn + wn * 32 + (lane & 3) * 2;
    float pa[4] = {0.f, 0.f, 0.f, 0.f};
    float pd[4] = {0.f, 0.f, 0.f, 0.f};
#pragma unroll
    for (int mt = 0; mt < 2; mt++)
#pragma unroll
        for (int nt = 0; nt < 4; nt++) {
            int r = row0 + mt * 16;
            int c = col0 + nt * 8;
            float b0 = bias[c], b1 = bias[c + 1];
            float v00 = acc[mt][nt][0] + b0, v01 = acc[mt][nt][1] + b1;
            float v10 = acc[mt][nt][2] + b0, v11 = acc[mt][nt][3] + b1;
            if (mode == 1) {
                float u0 = upon[c], u1 = upon[c + 1];
                float d0 = down[c], d1 = down[c + 1];
                pa[mt * 2 + 0] += v00 * u0 + v01 * u1;
                pa[mt * 2 + 1] += v10 * u0 + v11 * u1;
                pd[mt * 2 + 0] += v00 * d0 + v01 * d1;
                pd[mt * 2 + 1] += v10 * d0 + v11 * d1;
            } else if (mode == 2) {
                float d0 = down[c], d1 = down[c + 1];
                pd[mt * 2 + 0] += v00 * d0 + v01 * d1;
                pd[mt * 2 + 1] += v10 * d0 + v11 * d1;
            }
            float2 o0 = make_float2(v00, v01);
            float2 o1 = make_float2(v10, v11);
            if (dotanh) {
                o0.x = tanhf(o0.x); o0.y = tanhf(o0.y);
                o1.x = tanhf(o1.x); o1.y = tanhf(o1.y);
            }
            *(float2*)(C + (size_t)r * 256 + c)       = o0;
            *(float2*)(C + (size_t)(r + 8) * 256 + c) = o1;
        }

    if (mode) {
#pragma unroll
        for (int j = 0; j < 4; j++) {
            pa[j] += __shfl_xor_sync(0xFFFFFFFFu, pa[j], 1);
            pa[j] += __shfl_xor_sync(0xFFFFFFFFu, pa[j], 2);
            pd[j] += __shfl_xor_sync(0xFFFFFFFFu, pd[j], 1);
            pd[j] += __shfl_xor_sync(0xFFFFFFFFu, pd[j], 2);
        }
        if ((lane & 3) == 0) {
            const int hn = (bn >> 5) + wn;
#pragma unroll
            for (int j = 0; j < 4; j++) {
                int row = row0 + (j >> 1) * 16 + (j & 1) * 8;
                if (mode == 1) {
                    int b = row >> 12, l = row & 4095;
                    g_uq[((size_t)(b * NHq + hn)) * Lq + l] = pa[j];
                    g_ds[((size_t)(b * NHq + hn)) * Lq + l] = pd[j];
                } else {
                    int b = row >> 6, t = row & 63;
                    g_dt[(b * NHq + hn) * Tq + t] = pd[j];
                }
            }
        }
    }
}

// ---------------- attention core v7: fp16 single-mma, halved smem ---------------
#define OFF_XT    0        // crossT 32 x 20
#define OFF_CHa   640      // CH 80 x 20
#define OFF_TY    2240     // types 64 x 20
#define OFF_CQ    3520     // CQ 64 x 20  -> pool ends 4800
#define OFF_WT    0        // alias: Wt 64 x 36
#define OFF_WW    2304     // alias: Wwin 64 x 44 -> alias pool ends 5120
#define OFF_TT    5120     // typesT 32 x 36
#define OFF_CT    6272     // CHT 32 x 44
#define OFF_LT    7680     // logitsT float [64][68]
#define OFF_G     12032    // band G float [64][21]
#define OFF_UQ    13376
#define OFF_DS    13456
#define OFF_MK    13536
#define OFF_DT    13616
#define SMEM_UINTS 13680
#define ATTN_SMEM_BYTES (SMEM_UINTS * 4)

__global__ __launch_bounds__(512, 3) void attn_f16_kernel(
    const float* __restrict__ cross, const void* __restrict__ maskp,
    const float* __restrict__ context)
{
    extern __shared__ unsigned SU[];
    float* SF = (float*)SU;
    __half* SH = (__half*)SU;
    const int tid = threadIdx.x, wid = tid >> 5, lane = tid & 31;
    const int n = blockIdx.y, b = blockIdx.z;
    const int l0 = blockIdx.x * 64;
    const int mmode = mask_mode(maskp);
    const int bnL = (b * NHq + n) * Lq;
    const long maskbase = (long)b * Lq;

    // ---------------- stage row-major (packed f16x2 stores) ----------------
    {
        const int j2 = lane & 15, rs = lane >> 4;
#pragma unroll
        for (int it = 0; it < 2; it++) {
            int t = it * 32 + wid * 2 + rs;
            float2 v = *(const float2*)(g_types_h + (size_t)(b * Tq + t) * Hq + n * 32 + 2 * j2);
            SU[OFF_TY + t * 20 + j2] = pack_f16x2(v.x, v.y);
        }
        for (int r = wid * 2 + rs; r < 80; r += 32) {
            int row = l0 + r; if (row > Lq - 1) row = Lq - 1;
            float2 v = *(const float2*)(g_ch + (size_t)(b * Lq + row) * Hq + n * 32 + 2 * j2);
            SU[OFF_CHa + r * 20 + j2] = pack_f16x2(v.x, v.y);
        }
    }
    for (int d = wid; d < 32; d += 16) {
        float v = cross[(size_t)(n * Dq + d) * Dq + lane];
        SH[(OFF_XT << 1) + lane * 40 + d] = __float2half_rn(v);
    }
    for (int i = tid; i < 80; i += 512) {
        int ru = l0 + i; if (ru > Lq - 1) ru = Lq - 1;
        SF[OFF_UQ + i] = g_uq[bnL + ru];
        SF[OFF_MK + i] = mask_at(maskp, mmode, maskbase + ru) ? 1.f : 0.f;
        int rd = l0 + i - 16; if (rd < 0) rd = 0;
        SF[OFF_DS + i] = g_ds[bnL + rd];
    }
    for (int i = tid; i < 64; i += 512) SF[OFF_DT + i] = g_dt[(b * NHq + n) * Tq + i];
    __syncthreads();

    // ---------------- build typesT / CHT from packed row-major arrays ---------
    {
        const int dd = ((wid & 3) << 3) + (lane >> 2);
        const int kpb = ((wid >> 2) << 2) + (lane & 3);
        const unsigned sel = (dd & 1) ? 0x7632u : 0x5410u;
#pragma unroll
        for (int it = 0; it < 2; it++) {
            int kp = kpb + it * 16;
            int u0 = OFF_TY + kp * 40 + (dd >> 1);
            SU[OFF_TT + dd * 36 + kp] = __byte_perm(SU[u0], SU[u0 + 20], sel);
        }
#pragma unroll
        for (int it = 0; it < 3; it++) {
            int kp = kpb + it * 16;
            if (kp < 40) {
                int u0 = OFF_CHa + kp * 40 + (dd >> 1);
                SU[OFF_CT + dd * 44 + kp] = __byte_perm(SU[u0], SU[u0 + 20], sel);
            }
        }
    }
    __syncthreads();

    // ---------------- phase A: CQ(64x32) = CH @ crossT (16 warps) ----------------
    {
        const int mt = wid >> 2, nh = wid & 3;
        float acc[4] = {0, 0, 0, 0};
#pragma unroll
        for (int k16 = 0; k16 < 2; k16++) {
            unsigned a[4], bb[2];
            gatherA16(SU + OFF_CHa, 20, mt * 16, k16 * 8, lane, a);
            gatherB16(SU + OFF_XT, 20, nh * 8, k16 * 8, lane, bb);
            mma16f(acc, a, bb);
        }
        const int rlo = mt * 16 + (lane >> 2);
        const int cp = nh * 4 + (lane & 3);
        SU[OFF_CQ + rlo * 20 + cp]       = pack_f16x2(acc[0], acc[1]);
        SU[OFF_CQ + (rlo + 8) * 20 + cp] = pack_f16x2(acc[2], acc[3]);
    }
    __syncthreads();

    // ---------------- phase B ----------------
    if (wid < 8) {     // logitsT
        const int mt = wid >> 1, half = wid & 1;
        float acc2[4][4];
#pragma unroll
        for (int i = 0; i < 4; i++)
#pragma unroll
            for (int r = 0; r < 4; r++) acc2[i][r] = 0.f;
#pragma unroll
        for (int k16 = 0; k16 < 2; k16++) {
            unsigned a[4];
            gatherA16(SU + OFF_CQ, 20, mt * 16, k16 * 8, lane, a);
#pragma unroll
            for (int j = 0; j < 4; j++) {
                unsigned bb[2];
                gatherB16(SU + OFF_TY, 20, (half * 4 + j) * 8, k16 * 8, lane, bb);
                mma16f(acc2[j], a, bb);
            }
        }
        const int rlo = mt * 16 + (lane >> 2);
#pragma unroll
        for (int j = 0; j < 4; j++) {
            int c0 = (half * 4 + j) * 8 + 2 * (lane & 3);
            *(float2*)&SF[OFF_LT + rlo * 68 + c0]       = make_float2(acc2[j][0], acc2[j][1]);
            *(float2*)&SF[OFF_LT + (rlo + 8) * 68 + c0] = make_float2(acc2[j][2], acc2[j][3]);
        }
    } else {           // band G
        const int w = wid - 8;
        const int rb = w >> 1, half = w & 1;
        float accg[2][4];
#pragma unroll
        for (int i = 0; i < 2; i++)
#pragma unroll
            for (int r = 0; r < 4; r++) accg[i][r] = 0.f;
#pragma unroll
        for (int k16 = 0; k16 < 2; k16++) {
            unsigned a[4];
            gatherA16(SU + OFF_CQ, 20, rb * 16, k16 * 8, lane, a);
#pragma unroll
            for (int j = 0; j < 2; j++) {
                unsigned bb[2];
                gatherB16(SU + OFF_CHa, 20, rb * 16 + (half * 2 + j) * 8, k16 * 8, lane, bb);
                mma16f(accg[j], a, bb);
            }
        }
        const int rlo = rb * 16 + (lane >> 2), rhi = rlo + 8;
#pragma unroll
        for (int j = 0; j < 2; j++) {
            int m0 = rb * 16 + (half * 2 + j) * 8 + 2 * (lane & 3);
            int k;
            k = m0 - rlo;     if (k >= 0 && k <= 16) SF[OFF_G + rlo * 21 + k] = accg[j][0];
            k = m0 + 1 - rlo; if (k >= 0 && k <= 16) SF[OFF_G + rlo * 21 + k] = accg[j][1];
            k = m0 - rhi;     if (k >= 0 && k <= 16) SF[OFF_G + rhi * 21 + k] = accg[j][2];
            k = m0 + 1 - rhi; if (k >= 0 && k <= 16) SF[OFF_G + rhi * 21 + k] = accg[j][3];
        }
    }
    __syncthreads();

    // ---------------- zero Wwin pool (aliases dead CQ region) -----------------
    {
        uint4 z = make_uint4(0, 0, 0, 0);
        for (int i = tid; i < 704; i += 512) ((uint4*)(SU + OFF_WW))[i] = z;
    }
    __syncthreads();

    // ---------------- softmax (4 rows per warp) ----------------
    for (int i = 0; i < 4; i++) {
        const int r = wid * 4 + i;
        const int l = l0 + r;
        const float uq_l = SF[OFF_UQ + r];

        float lt0 = leaky(uq_l + SF[OFF_DT + lane]      + SF[OFF_LT + r * 68 + lane]);
        float lt1 = leaky(uq_l + SF[OFF_DT + lane + 32] + SF[OFF_LT + r * 68 + 32 + lane]);

        const int ku = (lane <= 16) ? 0 : lane - 16;
        const int kd = (lane < 16) ? lane - 16 : 0;
        const bool ok = (l + kd >= 0) && (l + ku < Lq);
        const bool mk = ok && (SF[OFF_MK + r + ku] != 0.f);
        float lg = leaky(SF[OFF_UQ + r + ku] + SF[OFF_DS + r + kd + 16] + SF[OFF_G + r * 21 + ku]);
        float lw = mk ? lg : MASK_FILL;

        float lw2 = -INFINITY;
        if (lane == 0) {
            const bool ok2 = (l + 16 < Lq);
            const bool mk2 = ok2 && (SF[OFF_MK + r + 16] != 0.f);
            float lg2 = leaky(SF[OFF_UQ + r + 16] + SF[OFF_DS + r + 16] + SF[OFF_G + r * 21 + 16]);
            lw2 = mk2 ? lg2 : MASK_FILL;
        }

        float mx = fmaxf(fmaxf(lt0, lt1), lw);
        if (lane == 0) mx = fmaxf(mx, lw2);
#pragma unroll
        for (int o = 16; o; o >>= 1) mx = fmaxf(mx, __shfl_xor_sync(0xFFFFFFFFu, mx, o));
        float e0 = __expf(lt0 - mx), e1 = __expf(lt1 - mx), ew = __expf(lw - mx);
        float ew2 = (lane == 0) ? __expf(lw2 - mx) : 0.f;
        float sm = e0 + e1 + ew + ew2;
#pragma unroll
        for (int o = 16; o; o >>= 1) sm += __shfl_xor_sync(0xFFFFFFFFu, sm, o);
        const float inv = 1.0f / sm;

        SH[(OFF_WT << 1) + r * 72 + lane]      = __float2half_rn(e0 * inv);
        SH[(OFF_WT << 1) + r * 72 + lane + 32] = __float2half_rn(e1 * inv);

        float wwl = ew * inv;
        float wband = (lane <= 16) ? wwl : 0.f;
#pragma unroll
        for (int o = 16; o; o >>= 1) wband += __shfl_xor_sync(0xFFFFFFFFu, wband, o);
        if (lane == 0) {
            SH[(OFF_WW << 1) + r * 88 + r]      = __float2half_rn(wband);
            SH[(OFF_WW << 1) + r * 88 + r + 16] = __float2half_rn(ew2 * inv);
        } else if (lane >= 17) {
            SH[(OFF_WW << 1) + r * 88 + r + (lane - 16)] = __float2half_rn(wwl);
        }
    }
    __syncthreads();

    // ---------------- update (16 warps; window part band-limited to K=32) ------
    {
        const int mt = wid & 3;
        const int nth = wid >> 2;
        float acc[4] = {0, 0, 0, 0};
#pragma unroll
        for (int k16 = 0; k16 < 4; k16++) {
            unsigned a[4], bb[2];
            gatherA16(SU + OFF_WT, 36, mt * 16, k16 * 8, lane, a);
            gatherB16(SU + OFF_TT, 36, nth * 8, k16 * 8, lane, bb);
            mma16f(acc, a, bb);
        }
#pragma unroll
        for (int k16 = 0; k16 < 2; k16++) {   // band: kpairs [mt*8, mt*8+16)
            const int KP0 = mt * 8 + k16 * 8;
            unsigned a[4], bb[2];
            gatherA16(SU + OFF_WW, 44, mt * 16, KP0, lane, a);
            gatherB16(SU + OFF_CT, 44, nth * 8, KP0, lane, bb);
            mma16f(acc, a, bb);
        }
        const int llo = l0 + mt * 16 + (lane >> 2);
        const int col = n * 32 + nth * 8 + 2 * (lane & 3);
        size_t g0 = (size_t)(b * Lq + llo) * Hq + col;
        size_t g1 = (size_t)(b * Lq + llo + 8) * Hq + col;
        float2 c0 = *(const float2*)&context[g0];
        float2 c1 = *(const float2*)&context[g1];
        *(float2*)&g_U[g0] = make_float2(acc[0] + c0.x, acc[1] + c0.y);
        *(float2*)&g_U[g1] = make_float2(acc[2] + c1.x, acc[3] + c1.y);
    }
}

// ---------------- launch ----------------
extern "C" void kernel_launch(void* const* d_in, const int* in_sizes, int n_in,
                              void* d_out, int out_size)
{
    (void)in_sizes; (void)n_in; (void)out_size;
    const float* context   = (const float*)d_in[0];
    const float* types     = (const float*)d_in[1];
    const void*  cmask     = d_in[2];
    const float* W_types   = (const float*)d_in[3];
    const float* b_types   = (const float*)d_in[4];
    const float* W_context = (const float*)d_in[5];
    const float* b_context = (const float*)d_in[6];
    const float* upon      = (const float*)d_in[7];
    const float* down      = (const float*)d_in[8];
    const float* cross     = (const float*)d_in[9];
    const float* W_out     = (const float*)d_in[10];
    const float* b_out     = (const float*)d_in[11];
    float* out = (float*)d_out;

    float *p_types_h, *p_ch, *p_U;
    cudaGetSymbolAddress((void**)&p_types_h, g_types_h);
    cudaGetSymbolAddress((void**)&p_ch, g_ch);
    cudaGetSymbolAddress((void**)&p_U, g_U);

    cudaFuncSetAttribute(attn_f16_kernel,
                         cudaFuncAttributeMaxDynamicSharedMemorySize, ATTN_SMEM_BYTES);

    prep_weights<<<dim3(8, 8, 3), 256>>>(W_types, W_context, W_out);
    gemm_bf16x3<<<dim3(4, 2), 256>>>(types, 0, b_types, p_types_h, 0, 2, upon, down);
    gemm_bf16x3<<<dim3(4, 128), 256>>>(context, 1, b_context, p_ch, 0, 1, upon, down);
    attn_f16_kernel<<<dim3(Lq / 64, NHq, Bq), 512, ATTN_SMEM_BYTES>>>(cross, cmask, context);
    gemm_bf16x3<<<dim3(4, 128), 256>>>(p_U, 2, b_out, out, 1, 0, upon, down);
}

// round 15
// speedup vs baseline: 1.7684x; 1.2898x over previous
#include <cuda_runtime.h>
#include <cuda_fp16.h>
#include <math.h>

#define Bq 4
#define Lq 4096
#define Hq 256
#define NHq 8
#define Tq 64
#define Dq 32
#define WINq 16
#define NEG_SLOPE 5.0f
#define MASK_FILL -1e12f

// ---------------- scratch (device globals; no allocation allowed) ----------------
__device__ float g_types_h[Bq * Tq * Hq];
__device__ float g_ch[Bq * Lq * Hq];
__device__ float g_U[Bq * Lq * Hq];
__device__ float g_uq[Bq * NHq * Lq];
__device__ float g_ds[Bq * NHq * Lq];
__device__ float g_dt[Bq * NHq * Tq];
__device__ unsigned g_WtF16[3 * 256 * 128];   // transposed f16x2 weights [w][n][kpair]

__device__ __forceinline__ float leaky(float x) { return x >= 0.f ? x : NEG_SLOPE * x; }

__device__ __forceinline__ unsigned pack_f16x2(float lo_elem, float hi_elem) {
    unsigned r;
    asm("cvt.rn.f16x2.f32 %0, %1, %2;" : "=r"(r) : "f"(hi_elem), "f"(lo_elem));
    return r;
}

__device__ __forceinline__ void mma16f(float c[4], const unsigned a[4], const unsigned b[2]) {
    asm volatile(
        "mma.sync.aligned.m16n8k16.row.col.f32.f16.f16.f32 "
        "{%0,%1,%2,%3}, {%4,%5,%6,%7}, {%8,%9}, {%0,%1,%2,%3};"
        : "+f"(c[0]), "+f"(c[1]), "+f"(c[2]), "+f"(c[3])
        : "r"(a[0]), "r"(a[1]), "r"(a[2]), "r"(a[3]), "r"(b[0]), "r"(b[1]));
}

// ---- ldmatrix-based fragment loads (rows 16B-aligned: strides 20/36/44 uints) ----
__device__ __forceinline__ void gatherA16(const unsigned* U, int stride,
                                          int R0, int KP0, int lane, unsigned a[4]) {
    int grp = lane >> 3, lr = lane & 7;
    int row = R0 + lr + ((grp & 1) << 3);
    int kp  = KP0 + ((grp >> 1) << 2);
    unsigned addr = (unsigned)__cvta_generic_to_shared(U + row * stride + kp);
    asm volatile("ldmatrix.sync.aligned.m8n8.x4.shared.b16 {%0,%1,%2,%3}, [%4];"
                 : "=r"(a[0]), "=r"(a[1]), "=r"(a[2]), "=r"(a[3]) : "r"(addr));
}
__device__ __forceinline__ void gatherB16(const unsigned* U, int stride,
                                          int N0, int KP0, int lane, unsigned bb[2]) {
    int grp = (lane >> 3) & 1, lr = lane & 7;
    int row = N0 + lr;
    int kp  = KP0 + (grp << 2);
    unsigned addr = (unsigned)__cvta_generic_to_shared(U + row * stride + kp);
    asm volatile("ldmatrix.sync.aligned.m8n8.x2.shared.b16 {%0,%1}, [%2];"
                 : "=r"(bb[0]), "=r"(bb[1]) : "r"(addr));
}

__device__ __forceinline__ int mask_mode(const void* m) {
    unsigned u = *(const unsigned*)m;
    if (u == 0x01010101u) return 0;
    if (u == 0x3F800000u) return 2;
    return 1;
}
__device__ __forceinline__ bool mask_at(const void* m, int mode, long idx) {
    if (mode == 0) return ((const unsigned char*)m)[idx] != 0;
    if (mode == 1) return ((const int*)m)[idx] != 0;
    return ((const float*)m)[idx] != 0.f;
}

// ---------------- prep: transpose + f16-pack the three 256x256 weights ---------
__global__ __launch_bounds__(256) void prep_weights(
    const float* __restrict__ W0, const float* __restrict__ W1,
    const float* __restrict__ W2)
{
    __shared__ float s[32][33];
    const int w = blockIdx.z;
    const float* W = (w == 0) ? W0 : (w == 1) ? W1 : W2;
    const int k0 = blockIdx.x * 32, n0 = blockIdx.y * 32;
    const int tid = threadIdx.x;
#pragma unroll
    for (int it = 0; it < 4; it++) {
        int idx = it * 256 + tid;
        int kr = idx >> 5, nc = idx & 31;
        s[kr][nc] = W[(size_t)(k0 + kr) * 256 + n0 + nc];
    }
    __syncthreads();
#pragma unroll
    for (int it = 0; it < 2; it++) {
        int idx = it * 256 + tid;
        int nn = idx >> 4, kp = idx & 15;
        size_t o = (size_t)(w * 256 + n0 + nn) * 128 + (k0 >> 1) + kp;
        g_WtF16[o] = pack_f16x2(s[2 * kp][nn], s[2 * kp + 1][nn]);
    }
}

// ---------------- fp16 GEMM + fused row-dot epilogue ----------------------------
// mode: 0 = plain (+tanh per flag), 1 = also uq/ds (rows b*L+l), 2 = dt (rows b*T+t)
__global__ __launch_bounds__(256) void gemm_f16(
    const float* __restrict__ A, int wsel,
    const float* __restrict__ bias, float* __restrict__ C,
    int dotanh, int mode,
    const float* __restrict__ upon, const float* __restrict__ down)
{
    __shared__ unsigned sA[128 * 20];
    __shared__ unsigned sB[64 * 20];

    const int tid = threadIdx.x;
    const int wid = tid >> 5, lane = tid & 31;
    const int wm = wid >> 1, wn = wid & 1;
    const int bm = blockIdx.y * 128;
    const int bn = blockIdx.x * 64;
    const unsigned* WF = g_WtF16 + (size_t)wsel * 256 * 128;

    float acc[2][4][4];
#pragma unroll
    for (int mt = 0; mt < 2; mt++)
#pragma unroll
        for (int nt = 0; nt < 4; nt++)
#pragma unroll
            for (int r = 0; r < 4; r++) acc[mt][nt][r] = 0.f;

    for (int chunk = 0; chunk < 8; chunk++) {
        const int kc0 = chunk * 32;
#pragma unroll
        for (int i = 0; i < 4; i++) {
            int fidx = i * 256 + tid;
            int row = fidx >> 3, col4 = fidx & 7;
            float4 v = *(const float4*)(A + (size_t)(bm + row) * 256 + kc0 + col4 * 4);
            int o = row * 20 + col4 * 2;
            *(uint2*)&sA[o] = make_uint2(pack_f16x2(v.x, v.y), pack_f16x2(v.z, v.w));
        }
#pragma unroll
        for (int i = 0; i < 2; i++) {
            int fidx = i * 256 + tid;
            int row = fidx >> 3, j = fidx & 7;
            size_t src = (size_t)(bn + row) * 128 + (kc0 >> 1) + j * 2;
            *(uint2*)&sB[row * 20 + j * 2] = *(const uint2*)&WF[src];
        }
        __syncthreads();
#pragma unroll
        for (int k16 = 0; k16 < 2; k16++) {
            unsigned a[2][4];
#pragma unroll
            for (int mt = 0; mt < 2; mt++)
                gatherA16(sA, 20, wm * 32 + mt * 16, k16 * 8, lane, a[mt]);
#pragma unroll
            for (int nt = 0; nt < 4; nt++) {
                unsigned bb[2];
                gatherB16(sB, 20, wn * 32 + nt * 8, k16 * 8, lane, bb);
#pragma unroll
                for (int mt = 0; mt < 2; mt++) mma16f(acc[mt][nt], a[mt], bb);
            }
        }
        __syncthreads();
    }

    const int row0 = bm + wm * 32 + (lane >> 2);
    const int col0 = bn + wn * 32 + (lane & 3) * 2;
    float pa[4] = {0.f, 0.f, 0.f, 0.f};
    float pd[4] = {0.f, 0.f, 0.f, 0.f};
#pragma unroll
    for (int mt = 0; mt < 2; mt++)
#pragma unroll
        for (int nt = 0; nt < 4; nt++) {
            int r = row0 + mt * 16;
            int c = col0 + nt * 8;
            float b0 = bias[c], b1 = bias[c + 1];
            float v00 = acc[mt][nt][0] + b0, v01 = acc[mt][nt][1] + b1;
            float v10 = acc[mt][nt][2] + b0, v11 = acc[mt][nt][3] + b1;
            if (mode == 1) {
                float u0 = upon[c], u1 = upon[c + 1];
                float d0 = down[c], d1 = down[c + 1];
                pa[mt * 2 + 0] += v00 * u0 + v01 * u1;
                pa[mt * 2 + 1] += v10 * u0 + v11 * u1;
                pd[mt * 2 + 0] += v00 * d0 + v01 * d1;
                pd[mt * 2 + 1] += v10 * d0 + v11 * d1;
            } else if (mode == 2) {
                float d0 = down[c], d1 = down[c + 1];
                pd[mt * 2 + 0] += v00 * d0 + v01 * d1;
                pd[mt * 2 + 1] += v10 * d0 + v11 * d1;
            }
            float2 o0 = make_float2(v00, v01);
            float2 o1 = make_float2(v10, v11);
            if (dotanh) {
                o0.x = tanhf(o0.x); o0.y = tanhf(o0.y);
                o1.x = tanhf(o1.x); o1.y = tanhf(o1.y);
            }
            *(float2*)(C + (size_t)r * 256 + c)       = o0;
            *(float2*)(C + (size_t)(r + 8) * 256 + c) = o1;
        }

    if (mode) {
#pragma unroll
        for (int j = 0; j < 4; j++) {
            pa[j] += __shfl_xor_sync(0xFFFFFFFFu, pa[j], 1);
            pa[j] += __shfl_xor_sync(0xFFFFFFFFu, pa[j], 2);
            pd[j] += __shfl_xor_sync(0xFFFFFFFFu, pd[j], 1);
            pd[j] += __shfl_xor_sync(0xFFFFFFFFu, pd[j], 2);
        }
        if ((lane & 3) == 0) {
            const int hn = (bn >> 5) + wn;
#pragma unroll
            for (int j = 0; j < 4; j++) {
                int row = row0 + (j >> 1) * 16 + (j & 1) * 8;
                if (mode == 1) {
                    int b = row >> 12, l = row & 4095;
                    g_uq[((size_t)(b * NHq + hn)) * Lq + l] = pa[j];
                    g_ds[((size_t)(b * NHq + hn)) * Lq + l] = pd[j];
                } else {
                    int b = row >> 6, t = row & 63;
                    g_dt[(b * NHq + hn) * Tq + t] = pd[j];
                }
            }
        }
    }
}

// ---------------- attention core v7: fp16 single-mma (R14, unchanged) -----------
#define OFF_XT    0
#define OFF_CHa   640
#define OFF_TY    2240
#define OFF_CQ    3520
#define OFF_WT    0
#define OFF_WW    2304
#define OFF_TT    5120
#define OFF_CT    6272
#define OFF_LT    7680
#define OFF_G     12032
#define OFF_UQ    13376
#define OFF_DS    13456
#define OFF_MK    13536
#define OFF_DT    13616
#define SMEM_UINTS 13680
#define ATTN_SMEM_BYTES (SMEM_UINTS * 4)

__global__ __launch_bounds__(512, 3) void attn_f16_kernel(
    const float* __restrict__ cross, const void* __restrict__ maskp,
    const float* __restrict__ context)
{
    extern __shared__ unsigned SU[];
    float* SF = (float*)SU;
    __half* SH = (__half*)SU;
    const int tid = threadIdx.x, wid = tid >> 5, lane = tid & 31;
    const int n = blockIdx.y, b = blockIdx.z;
    const int l0 = blockIdx.x * 64;
    const int mmode = mask_mode(maskp);
    const int bnL = (b * NHq + n) * Lq;
    const long maskbase = (long)b * Lq;

    // ---------------- stage row-major (packed f16x2 stores) ----------------
    {
        const int j2 = lane & 15, rs = lane >> 4;
#pragma unroll
        for (int it = 0; it < 2; it++) {
            int t = it * 32 + wid * 2 + rs;
            float2 v = *(const float2*)(g_types_h + (size_t)(b * Tq + t) * Hq + n * 32 + 2 * j2);
            SU[OFF_TY + t * 20 + j2] = pack_f16x2(v.x, v.y);
        }
        for (int r = wid * 2 + rs; r < 80; r += 32) {
            int row = l0 + r; if (row > Lq - 1) row = Lq - 1;
            float2 v = *(const float2*)(g_ch + (size_t)(b * Lq + row) * Hq + n * 32 + 2 * j2);
            SU[OFF_CHa + r * 20 + j2] = pack_f16x2(v.x, v.y);
        }
    }
    for (int d = wid; d < 32; d += 16) {
        float v = cross[(size_t)(n * Dq + d) * Dq + lane];
        SH[(OFF_XT << 1) + lane * 40 + d] = __float2half_rn(v);
    }
    for (int i = tid; i < 80; i += 512) {
        int ru = l0 + i; if (ru > Lq - 1) ru = Lq - 1;
        SF[OFF_UQ + i] = g_uq[bnL + ru];
        SF[OFF_MK + i] = mask_at(maskp, mmode, maskbase + ru) ? 1.f : 0.f;
        int rd = l0 + i - 16; if (rd < 0) rd = 0;
        SF[OFF_DS + i] = g_ds[bnL + rd];
    }
    for (int i = tid; i < 64; i += 512) SF[OFF_DT + i] = g_dt[(b * NHq + n) * Tq + i];
    __syncthreads();

    // ---------------- build typesT / CHT from packed row-major arrays ---------
    {
        const int dd = ((wid & 3) << 3) + (lane >> 2);
        const int kpb = ((wid >> 2) << 2) + (lane & 3);
        const unsigned sel = (dd & 1) ? 0x7632u : 0x5410u;
#pragma unroll
        for (int it = 0; it < 2; it++) {
            int kp = kpb + it * 16;
            int u0 = OFF_TY + kp * 40 + (dd >> 1);
            SU[OFF_TT + dd * 36 + kp] = __byte_perm(SU[u0], SU[u0 + 20], sel);
        }
#pragma unroll
        for (int it = 0; it < 3; it++) {
            int kp = kpb + it * 16;
            if (kp < 40) {
                int u0 = OFF_CHa + kp * 40 + (dd >> 1);
                SU[OFF_CT + dd * 44 + kp] = __byte_perm(SU[u0], SU[u0 + 20], sel);
            }
        }
    }
    __syncthreads();

    // ---------------- phase A: CQ(64x32) = CH @ crossT (16 warps) ----------------
    {
        const int mt = wid >> 2, nh = wid & 3;
        float acc[4] = {0, 0, 0, 0};
#pragma unroll
        for (int k16 = 0; k16 < 2; k16++) {
            unsigned a[4], bb[2];
            gatherA16(SU + OFF_CHa, 20, mt * 16, k16 * 8, lane, a);
            gatherB16(SU + OFF_XT, 20, nh * 8, k16 * 8, lane, bb);
            mma16f(acc, a, bb);
        }
        const int rlo = mt * 16 + (lane >> 2);
        const int cp = nh * 4 + (lane & 3);
        SU[OFF_CQ + rlo * 20 + cp]       = pack_f16x2(acc[0], acc[1]);
        SU[OFF_CQ + (rlo + 8) * 20 + cp] = pack_f16x2(acc[2], acc[3]);
    }
    __syncthreads();

    // ---------------- phase B ----------------
    if (wid < 8) {     // logitsT
        const int mt = wid >> 1, half = wid & 1;
        float acc2[4][4];
#pragma unroll
        for (int i = 0; i < 4; i++)
#pragma unroll
            for (int r = 0; r < 4; r++) acc2[i][r] = 0.f;
#pragma unroll
        for (int k16 = 0; k16 < 2; k16++) {
            unsigned a[4];
            gatherA16(SU + OFF_CQ, 20, mt * 16, k16 * 8, lane, a);
#pragma unroll
            for (int j = 0; j < 4; j++) {
                unsigned bb[2];
                gatherB16(SU + OFF_TY, 20, (half * 4 + j) * 8, k16 * 8, lane, bb);
                mma16f(acc2[j], a, bb);
            }
        }
        const int rlo = mt * 16 + (lane >> 2);
#pragma unroll
        for (int j = 0; j < 4; j++) {
            int c0 = (half * 4 + j) * 8 + 2 * (lane & 3);
            *(float2*)&SF[OFF_LT + rlo * 68 + c0]       = make_float2(acc2[j][0], acc2[j][1]);
            *(float2*)&SF[OFF_LT + (rlo + 8) * 68 + c0] = make_float2(acc2[j][2], acc2[j][3]);
        }
    } else {           // band G
        const int w = wid - 8;
        const int rb = w >> 1, half = w & 1;
        float accg[2][4];
#pragma unroll
        for (int i = 0; i < 2; i++)
#pragma unroll
            for (int r = 0; r < 4; r++) accg[i][r] = 0.f;
#pragma unroll
        for (int k16 = 0; k16 < 2; k16++) {
            unsigned a[4];
            gatherA16(SU + OFF_CQ, 20, rb * 16, k16 * 8, lane, a);
#pragma unroll
            for (int j = 0; j < 2; j++) {
                unsigned bb[2];
                gatherB16(SU + OFF_CHa, 20, rb * 16 + (half * 2 + j) * 8, k16 * 8, lane, bb);
                mma16f(accg[j], a, bb);
            }
        }
        const int rlo = rb * 16 + (lane >> 2), rhi = rlo + 8;
#pragma unroll
        for (int j = 0; j < 2; j++) {
            int m0 = rb * 16 + (half * 2 + j) * 8 + 2 * (lane & 3);
            int k;
            k = m0 - rlo;     if (k >= 0 && k <= 16) SF[OFF_G + rlo * 21 + k] = accg[j][0];
            k = m0 + 1 - rlo; if (k >= 0 && k <= 16) SF[OFF_G + rlo * 21 + k] = accg[j][1];
            k = m0 - rhi;     if (k >= 0 && k <= 16) SF[OFF_G + rhi * 21 + k] = accg[j][2];
            k = m0 + 1 - rhi; if (k >= 0 && k <= 16) SF[OFF_G + rhi * 21 + k] = accg[j][3];
        }
    }
    __syncthreads();

    // ---------------- zero Wwin pool (aliases dead CQ region) -----------------
    {
        uint4 z = make_uint4(0, 0, 0, 0);
        for (int i = tid; i < 704; i += 512) ((uint4*)(SU + OFF_WW))[i] = z;
    }
    __syncthreads();

    // ---------------- softmax (4 rows per warp) ----------------
    for (int i = 0; i < 4; i++) {
        const int r = wid * 4 + i;
        const int l = l0 + r;
        const float uq_l = SF[OFF_UQ + r];

        float lt0 = leaky(uq_l + SF[OFF_DT + lane]      + SF[OFF_LT + r * 68 + lane]);
        float lt1 = leaky(uq_l + SF[OFF_DT + lane + 32] + SF[OFF_LT + r * 68 + 32 + lane]);

        const int ku = (lane <= 16) ? 0 : lane - 16;
        const int kd = (lane < 16) ? lane - 16 : 0;
        const bool ok = (l + kd >= 0) && (l + ku < Lq);
        const bool mk = ok && (SF[OFF_MK + r + ku] != 0.f);
        float lg = leaky(SF[OFF_UQ + r + ku] + SF[OFF_DS + r + kd + 16] + SF[OFF_G + r * 21 + ku]);
        float lw = mk ? lg : MASK_FILL;

        float lw2 = -INFINITY;
        if (lane == 0) {
            const bool ok2 = (l + 16 < Lq);
            const bool mk2 = ok2 && (SF[OFF_MK + r + 16] != 0.f);
            float lg2 = leaky(SF[OFF_UQ + r + 16] + SF[OFF_DS + r + 16] + SF[OFF_G + r * 21 + 16]);
            lw2 = mk2 ? lg2 : MASK_FILL;
        }

        float mx = fmaxf(fmaxf(lt0, lt1), lw);
        if (lane == 0) mx = fmaxf(mx, lw2);
#pragma unroll
        for (int o = 16; o; o >>= 1) mx = fmaxf(mx, __shfl_xor_sync(0xFFFFFFFFu, mx, o));
        float e0 = __expf(lt0 - mx), e1 = __expf(lt1 - mx), ew = __expf(lw - mx);
        float ew2 = (lane == 0) ? __expf(lw2 - mx) : 0.f;
        float sm = e0 + e1 + ew + ew2;
#pragma unroll
        for (int o = 16; o; o >>= 1) sm += __shfl_xor_sync(0xFFFFFFFFu, sm, o);
        const float inv = 1.0f / sm;

        SH[(OFF_WT << 1) + r * 72 + lane]      = __float2half_rn(e0 * inv);
        SH[(OFF_WT << 1) + r * 72 + lane + 32] = __float2half_rn(e1 * inv);

        float wwl = ew * inv;
        float wband = (lane <= 16) ? wwl : 0.f;
#pragma unroll
        for (int o = 16; o; o >>= 1) wband += __shfl_xor_sync(0xFFFFFFFFu, wband, o);
        if (lane == 0) {
            SH[(OFF_WW << 1) + r * 88 + r]      = __float2half_rn(wband);
            SH[(OFF_WW << 1) + r * 88 + r + 16] = __float2half_rn(ew2 * inv);
        } else if (lane >= 17) {
            SH[(OFF_WW << 1) + r * 88 + r + (lane - 16)] = __float2half_rn(wwl);
        }
    }
    __syncthreads();

    // ---------------- update (16 warps; window part band-limited to K=32) ------
    {
        const int mt = wid & 3;
        const int nth = wid >> 2;
        float acc[4] = {0, 0, 0, 0};
#pragma unroll
        for (int k16 = 0; k16 < 4; k16++) {
            unsigned a[4], bb[2];
            gatherA16(SU + OFF_WT, 36, mt * 16, k16 * 8, lane, a);
            gatherB16(SU + OFF_TT, 36, nth * 8, k16 * 8, lane, bb);
            mma16f(acc, a, bb);
        }
#pragma unroll
        for (int k16 = 0; k16 < 2; k16++) {
            const int KP0 = mt * 8 + k16 * 8;
            unsigned a[4], bb[2];
            gatherA16(SU + OFF_WW, 44, mt * 16, KP0, lane, a);
            gatherB16(SU + OFF_CT, 44, nth * 8, KP0, lane, bb);
            mma16f(acc, a, bb);
        }
        const int llo = l0 + mt * 16 + (lane >> 2);
        const int col = n * 32 + nth * 8 + 2 * (lane & 3);
        size_t g0 = (size_t)(b * Lq + llo) * Hq + col;
        size_t g1 = (size_t)(b * Lq + llo + 8) * Hq + col;
        float2 c0 = *(const float2*)&context[g0];
        float2 c1 = *(const float2*)&context[g1];
        *(float2*)&g_U[g0] = make_float2(acc[0] + c0.x, acc[1] + c0.y);
        *(float2*)&g_U[g1] = make_float2(acc[2] + c1.x, acc[3] + c1.y);
    }
}

// ---------------- launch ----------------
extern "C" void kernel_launch(void* const* d_in, const int* in_sizes, int n_in,
                              void* d_out, int out_size)
{
    (void)in_sizes; (void)n_in; (void)out_size;
    const float* context   = (const float*)d_in[0];
    const float* types     = (const float*)d_in[1];
    const void*  cmask     = d_in[2];
    const float* W_types   = (const float*)d_in[3];
    const float* b_types   = (const float*)d_in[4];
    const float* W_context = (const float*)d_in[5];
    const float* b_context = (const float*)d_in[6];
    const float* upon      = (const float*)d_in[7];
    const float* down      = (const float*)d_in[8];
    const float* cross     = (const float*)d_in[9];
    const float* W_out     = (const float*)d_in[10];
    const float* b_out     = (const float*)d_in[11];
    float* out = (float*)d_out;

    float *p_types_h, *p_ch, *p_U;
    cudaGetSymbolAddress((void**)&p_types_h, g_types_h);
    cudaGetSymbolAddress((void**)&p_ch, g_ch);
    cudaGetSymbolAddress((void**)&p_U, g_U);

    cudaFuncSetAttribute(attn_f16_kernel,
                         cudaFuncAttributeMaxDynamicSharedMemorySize, ATTN_SMEM_BYTES);

    prep_weights<<<dim3(8, 8, 3), 256>>>(W_types, W_context, W_out);
    gemm_f16<<<dim3(4, 2), 256>>>(types, 0, b_types, p_types_h, 0, 2, upon, down);
    gemm_f16<<<dim3(4, 128), 256>>>(context, 1, b_context, p_ch, 0, 1, upon, down);
    attn_f16_kernel<<<dim3(Lq / 64, NHq, Bq), 512, ATTN_SMEM_BYTES>>>(cross, cmask, context);
    gemm_f16<<<dim3(4, 128), 256>>>(p_U, 2, b_out, out, 1, 0, upon, down);
}